// round 1
// baseline (speedup 1.0000x reference)
#include <cuda_runtime.h>

#define BB   4
#define SQ   2048
#define DM   1024
#define NH   16
#define HD   64
#define BS   (BB*SQ)      // 8192 rows
#define N3   (3*DM)       // 3072

// ---------------- scratch (device globals; no allocation allowed) -----------
__device__ float g_q[(size_t)BB*NH*SQ*HD];   // [b,h,s,hd]
__device__ float g_k[(size_t)BB*NH*SQ*HD];
__device__ float g_v[(size_t)BB*NH*SQ*HD];
__device__ float g_att[(size_t)BS*DM];       // merged heads [b,s,D]

// ============================================================================
// QKV GEMM: C[8192,3072] = x[8192,1024] @ w[1024,3072] + b; scatter to q/k/v
// 128x128 tile, K-step 8, 256 threads, 8x8 per-thread microtile.
// ============================================================================
__global__ __launch_bounds__(256) void qkv_gemm(const float* __restrict__ x,
                                                const float* __restrict__ w,
                                                const float* __restrict__ bias)
{
    __shared__ float As[8][128];   // [k][m]
    __shared__ float Bsm[8][128];  // [k][n]

    const int tx  = threadIdx.x;
    const int m0  = blockIdx.y * 128;
    const int n0  = blockIdx.x * 128;

    const int a_row  = tx >> 1;          // 0..127
    const int a_col4 = (tx & 1) * 4;     // 0 or 4
    const int b_row  = tx >> 5;          // 0..7
    const int b_col4 = (tx & 31) * 4;    // 0..124

    const int ty  = tx >> 4;             // 0..15
    const int tix = tx & 15;             // 0..15
    const int mreg = ty * 8;
    const int nreg = tix * 8;

    float acc[8][8];
#pragma unroll
    for (int i = 0; i < 8; ++i)
#pragma unroll
        for (int j = 0; j < 8; ++j) acc[i][j] = 0.f;

    for (int k0 = 0; k0 < DM; k0 += 8) {
        float4 av = *(const float4*)(x + (size_t)(m0 + a_row) * DM + k0 + a_col4);
        As[a_col4 + 0][a_row] = av.x;
        As[a_col4 + 1][a_row] = av.y;
        As[a_col4 + 2][a_row] = av.z;
        As[a_col4 + 3][a_row] = av.w;
        *(float4*)&Bsm[b_row][b_col4] =
            *(const float4*)(w + (size_t)(k0 + b_row) * N3 + n0 + b_col4);
        __syncthreads();

#pragma unroll
        for (int kk = 0; kk < 8; ++kk) {
            float ar[8], br[8];
            float4 t;
            t = *(const float4*)&As[kk][mreg];     ar[0]=t.x; ar[1]=t.y; ar[2]=t.z; ar[3]=t.w;
            t = *(const float4*)&As[kk][mreg + 4]; ar[4]=t.x; ar[5]=t.y; ar[6]=t.z; ar[7]=t.w;
            t = *(const float4*)&Bsm[kk][nreg];    br[0]=t.x; br[1]=t.y; br[2]=t.z; br[3]=t.w;
            t = *(const float4*)&Bsm[kk][nreg + 4];br[4]=t.x; br[5]=t.y; br[6]=t.z; br[7]=t.w;
#pragma unroll
            for (int i = 0; i < 8; ++i)
#pragma unroll
                for (int j = 0; j < 8; ++j) acc[i][j] += ar[i] * br[j];
        }
        __syncthreads();
    }

    // epilogue: scatter into q/k/v laid out [b,h,s,hd]
#pragma unroll
    for (int i = 0; i < 8; ++i) {
        const int m = m0 + mreg + i;
        const int b = m >> 11;         // /2048
        const int s = m & 2047;
#pragma unroll
        for (int j = 0; j < 8; ++j) {
            const int n   = n0 + nreg + j;
            const float v = acc[i][j] + bias[n];
            const int seg = n >> 10;        // 0=q 1=k 2=v
            const int nn  = n & 1023;
            const int h   = nn >> 6;
            const int dd  = nn & 63;
            const size_t idx = ((((size_t)b * NH + h) * SQ + s) << 6) + dd;
            if (seg == 0)      g_q[idx] = v;
            else if (seg == 1) g_k[idx] = v;
            else               g_v[idx] = v;
        }
    }
}

// ============================================================================
// Flash attention (fp32, causal). One block per (q-tile of 64 rows, b*h).
// 256 threads: 16x16 grid, each thread 4x4 of the 64x64 score/output tiles.
// Dynamic smem: Qs[64][64] KsT[64][64] Vs[64][64] Ps[64][64] = 64 KB.
// ============================================================================
__global__ __launch_bounds__(256) void attn_kernel()
{
    extern __shared__ float sm[];
    float* Qs  = sm;              // [qrow][kd]
    float* KsT = sm + 4096;       // [kd][krow]
    float* Vs  = sm + 8192;       // [krow][hd]
    float* Ps  = sm + 12288;      // [qrow][krow]

    const int bh = blockIdx.y;             // 0..63
    const int qt = blockIdx.x;             // 0..31
    const int q0 = qt * 64;
    const float* Qg = g_q + (size_t)bh * SQ * HD;
    const float* Kg = g_k + (size_t)bh * SQ * HD;
    const float* Vg = g_v + (size_t)bh * SQ * HD;

    const int tx  = threadIdx.x;
    const int ty  = tx >> 4;               // 0..15  (q rows ty*4..+3)
    const int tix = tx & 15;               // 0..15  (cols tix*4..+3)

    // load Q tile, pre-scaled by 1/sqrt(hd)
    for (int i = tx; i < 1024; i += 256) {
        const int r = i >> 4, c4 = (i & 15) << 2;
        float4 v = *(const float4*)(Qg + (size_t)(q0 + r) * HD + c4);
        v.x *= 0.125f; v.y *= 0.125f; v.z *= 0.125f; v.w *= 0.125f;
        *(float4*)(Qs + r * HD + c4) = v;
    }

    float O[4][4];
#pragma unroll
    for (int i = 0; i < 4; ++i)
#pragma unroll
        for (int j = 0; j < 4; ++j) O[i][j] = 0.f;
    float mrow[4] = {-1e30f, -1e30f, -1e30f, -1e30f};
    float lrow[4] = {0.f, 0.f, 0.f, 0.f};

    for (int kt = 0; kt <= qt; ++kt) {
        const int k0 = kt * 64;
        __syncthreads();   // prev-iter PV done reading Vs/Ps; Q store visible (1st iter)

        for (int i = tx; i < 1024; i += 256) {
            const int r = i >> 4, c4 = (i & 15) << 2;
            float4 kv = *(const float4*)(Kg + (size_t)(k0 + r) * HD + c4);
            KsT[(c4 + 0) * 64 + r] = kv.x;
            KsT[(c4 + 1) * 64 + r] = kv.y;
            KsT[(c4 + 2) * 64 + r] = kv.z;
            KsT[(c4 + 3) * 64 + r] = kv.w;
            *(float4*)(Vs + r * HD + c4) =
                *(const float4*)(Vg + (size_t)(k0 + r) * HD + c4);
        }
        __syncthreads();

        // scores: sc[i][j] = sum_kd Qs[qrow][kd] * K[krow][kd]
        float sc[4][4];
#pragma unroll
        for (int i = 0; i < 4; ++i)
#pragma unroll
            for (int j = 0; j < 4; ++j) sc[i][j] = 0.f;

        for (int kd = 0; kd < 64; kd += 4) {
            float qv[4][4];
#pragma unroll
            for (int i = 0; i < 4; ++i) {
                float4 t = *(const float4*)(Qs + (ty * 4 + i) * HD + kd);
                qv[i][0] = t.x; qv[i][1] = t.y; qv[i][2] = t.z; qv[i][3] = t.w;
            }
#pragma unroll
            for (int kk = 0; kk < 4; ++kk) {
                float4 t = *(const float4*)(KsT + (kd + kk) * 64 + tix * 4);
                float kvv[4] = {t.x, t.y, t.z, t.w};
#pragma unroll
                for (int i = 0; i < 4; ++i)
#pragma unroll
                    for (int j = 0; j < 4; ++j) sc[i][j] += qv[i][kk] * kvv[j];
            }
        }

        if (kt == qt) {  // causal mask on the diagonal tile
#pragma unroll
            for (int i = 0; i < 4; ++i)
#pragma unroll
                for (int j = 0; j < 4; ++j)
                    if (tix * 4 + j > ty * 4 + i) sc[i][j] = -1e30f;
        }

        // online softmax
        float mt[4], scale[4], psum[4];
#pragma unroll
        for (int i = 0; i < 4; ++i) {
            mt[i] = fmaxf(fmaxf(sc[i][0], sc[i][1]), fmaxf(sc[i][2], sc[i][3]));
        }
#pragma unroll
        for (int off = 1; off < 16; off <<= 1) {
#pragma unroll
            for (int i = 0; i < 4; ++i)
                mt[i] = fmaxf(mt[i], __shfl_xor_sync(0xffffffffu, mt[i], off));
        }
#pragma unroll
        for (int i = 0; i < 4; ++i) {
            const float mnew = fmaxf(mrow[i], mt[i]);
            scale[i] = __expf(mrow[i] - mnew);
            mrow[i]  = mnew;
            psum[i]  = 0.f;
#pragma unroll
            for (int j = 0; j < 4; ++j) {
                const float p = __expf(sc[i][j] - mnew);
                sc[i][j] = p;
                psum[i] += p;
            }
        }
#pragma unroll
        for (int off = 1; off < 16; off <<= 1) {
#pragma unroll
            for (int i = 0; i < 4; ++i)
                psum[i] += __shfl_xor_sync(0xffffffffu, psum[i], off);
        }
#pragma unroll
        for (int i = 0; i < 4; ++i) {
            lrow[i] = lrow[i] * scale[i] + psum[i];
#pragma unroll
            for (int j = 0; j < 4; ++j) O[i][j] *= scale[i];
            *(float4*)(Ps + (ty * 4 + i) * 64 + tix * 4) =
                make_float4(sc[i][0], sc[i][1], sc[i][2], sc[i][3]);
        }
        __syncthreads();

        // O += P @ V
        for (int j2 = 0; j2 < 64; j2 += 4) {
            float pv[4][4];
#pragma unroll
            for (int i = 0; i < 4; ++i) {
                float4 t = *(const float4*)(Ps + (ty * 4 + i) * 64 + j2);
                pv[i][0] = t.x; pv[i][1] = t.y; pv[i][2] = t.z; pv[i][3] = t.w;
            }
#pragma unroll
            for (int kk = 0; kk < 4; ++kk) {
                float4 t = *(const float4*)(Vs + (j2 + kk) * HD + tix * 4);
                float vv[4] = {t.x, t.y, t.z, t.w};
#pragma unroll
                for (int i = 0; i < 4; ++i)
#pragma unroll
                    for (int j = 0; j < 4; ++j) O[i][j] += pv[i][kk] * vv[j];
            }
        }
    }

    // normalize + write merged-head layout [b, s, h*64 + d]
    const int b = bh >> 4, h = bh & 15;
#pragma unroll
    for (int i = 0; i < 4; ++i) {
        const float inv = 1.0f / lrow[i];
        float4 o = make_float4(O[i][0] * inv, O[i][1] * inv,
                               O[i][2] * inv, O[i][3] * inv);
        *(float4*)(g_att + ((size_t)b * SQ + q0 + ty * 4 + i) * DM
                   + h * 64 + tix * 4) = o;
    }
}

// ============================================================================
// Output projection: out[8192,1024] = g_att @ pw[1024,1024] + pb
// ============================================================================
__global__ __launch_bounds__(256) void proj_gemm(const float* __restrict__ w,
                                                 const float* __restrict__ bias,
                                                 float* __restrict__ out)
{
    __shared__ float As[8][128];
    __shared__ float Bsm[8][128];

    const int tx  = threadIdx.x;
    const int m0  = blockIdx.y * 128;
    const int n0  = blockIdx.x * 128;

    const int a_row  = tx >> 1;
    const int a_col4 = (tx & 1) * 4;
    const int b_row  = tx >> 5;
    const int b_col4 = (tx & 31) * 4;

    const int ty  = tx >> 4;
    const int tix = tx & 15;
    const int mreg = ty * 8;
    const int nreg = tix * 8;

    float acc[8][8];
#pragma unroll
    for (int i = 0; i < 8; ++i)
#pragma unroll
        for (int j = 0; j < 8; ++j) acc[i][j] = 0.f;

    for (int k0 = 0; k0 < DM; k0 += 8) {
        float4 av = *(const float4*)(g_att + (size_t)(m0 + a_row) * DM + k0 + a_col4);
        As[a_col4 + 0][a_row] = av.x;
        As[a_col4 + 1][a_row] = av.y;
        As[a_col4 + 2][a_row] = av.z;
        As[a_col4 + 3][a_row] = av.w;
        *(float4*)&Bsm[b_row][b_col4] =
            *(const float4*)(w + (size_t)(k0 + b_row) * DM + n0 + b_col4);
        __syncthreads();

#pragma unroll
        for (int kk = 0; kk < 8; ++kk) {
            float ar[8], br[8];
            float4 t;
            t = *(const float4*)&As[kk][mreg];     ar[0]=t.x; ar[1]=t.y; ar[2]=t.z; ar[3]=t.w;
            t = *(const float4*)&As[kk][mreg + 4]; ar[4]=t.x; ar[5]=t.y; ar[6]=t.z; ar[7]=t.w;
            t = *(const float4*)&Bsm[kk][nreg];    br[0]=t.x; br[1]=t.y; br[2]=t.z; br[3]=t.w;
            t = *(const float4*)&Bsm[kk][nreg + 4];br[4]=t.x; br[5]=t.y; br[6]=t.z; br[7]=t.w;
#pragma unroll
            for (int i = 0; i < 8; ++i)
#pragma unroll
                for (int j = 0; j < 8; ++j) acc[i][j] += ar[i] * br[j];
        }
        __syncthreads();
    }

#pragma unroll
    for (int i = 0; i < 8; ++i) {
        const int m = m0 + mreg + i;
#pragma unroll
        for (int j = 0; j < 8; j += 4) {
            const int n = n0 + nreg + j;
            float4 o = make_float4(acc[i][j] + bias[n],
                                   acc[i][j + 1] + bias[n + 1],
                                   acc[i][j + 2] + bias[n + 2],
                                   acc[i][j + 3] + bias[n + 3]);
            *(float4*)(out + (size_t)m * DM + n) = o;
        }
    }
}

// ============================================================================
extern "C" void kernel_launch(void* const* d_in, const int* in_sizes, int n_in,
                              void* d_out, int out_size)
{
    const float* x    = (const float*)d_in[0];
    const float* attw = (const float*)d_in[1];
    const float* attb = (const float*)d_in[2];
    const float* pw   = (const float*)d_in[3];
    const float* pb   = (const float*)d_in[4];
    float* out = (float*)d_out;

    cudaFuncSetAttribute(attn_kernel,
                         cudaFuncAttributeMaxDynamicSharedMemorySize, 65536);

    qkv_gemm<<<dim3(N3 / 128, BS / 128), 256>>>(x, attw, attb);
    attn_kernel<<<dim3(SQ / 64, BB * NH), 256, 65536>>>();
    proj_gemm<<<dim3(DM / 128, BS / 128), 256>>>(pw, pb, out);
}

// round 3
// speedup vs baseline: 1.1390x; 1.1390x over previous
#include <cuda_runtime.h>
#include <cstdint>

#define BB   4
#define SQ   2048
#define DM   1024
#define NH   16
#define HD   64
#define BS   (BB*SQ)      // 8192 rows
#define N3   (3*DM)       // 3072

typedef unsigned long long u64;
typedef unsigned int u32;

// ---------------- scratch (device globals; no allocation allowed) -----------
__device__ float g_q[(size_t)BB*NH*SQ*HD];   // [b,h,s,hd]
__device__ float g_k[(size_t)BB*NH*SQ*HD];
__device__ float g_v[(size_t)BB*NH*SQ*HD];
__device__ float g_att[(size_t)BS*DM];       // merged heads [b,s,D]

// ---------------- f32x2 packed helpers --------------------------------------
__device__ __forceinline__ u64 pk(float a, float b) {
    u64 r; asm("mov.b64 %0, {%1, %2};" : "=l"(r) : "f"(a), "f"(b)); return r;
}
__device__ __forceinline__ void upk(u64 v, float& a, float& b) {
    asm("mov.b64 {%0, %1}, %2;" : "=f"(a), "=f"(b) : "l"(v));
}
__device__ __forceinline__ u64 ffma2(u64 a, u64 b, u64 c) {
    u64 d; asm("fma.rn.f32x2 %0, %1, %2, %3;" : "=l"(d) : "l"(a), "l"(b), "l"(c));
    return d;
}
__device__ __forceinline__ u64 fmul2(u64 a, u64 b) {
    u64 d; asm("mul.rn.f32x2 %0, %1, %2;" : "=l"(d) : "l"(a), "l"(b));
    return d;
}
__device__ __forceinline__ void cp_async16(u32 smem, const void* g) {
    asm volatile("cp.async.cg.shared.global [%0], [%1], 16;" :: "r"(smem), "l"(g));
}
__device__ __forceinline__ void cp_commit() {
    asm volatile("cp.async.commit_group;");
}
__device__ __forceinline__ void cp_wait0() {
    asm volatile("cp.async.wait_group 0;");
}

// ============================================================================
// Pipelined SGEMM mainloop (f32x2): 128x128 tile, BK=16, 256 thr, 8x8 micro.
// As: [stage][k][m] (scalar-transposed from register staging)
// Bs: [stage][k][n] (cp.async, natural layout)
// ============================================================================
struct GemmAcc { u64 acc[8][4]; };

template<int LDB>
__device__ __forceinline__ void gemm_mainloop(const float* __restrict__ A,
                                              const float* __restrict__ Bg,
                                              int m0, int n0, int K,
                                              float (*As)[16][128],
                                              float (*Bs)[16][128],
                                              GemmAcc& R)
{
    const int tx = threadIdx.x;
    const int ty  = tx >> 4;
    const int tix = tx & 15;
    const int mreg = ty * 8;
    const int nreg = tix * 8;

    const int a_row = tx >> 1;
    const int a_k8  = (tx & 1) * 8;

#pragma unroll
    for (int i = 0; i < 8; ++i)
#pragma unroll
        for (int j = 0; j < 4; ++j) R.acc[i][j] = 0ull;

    // ---- prologue: stage 0
    float4 av0 = *(const float4*)(A + (size_t)(m0 + a_row) * K + a_k8);
    float4 av1 = *(const float4*)(A + (size_t)(m0 + a_row) * K + a_k8 + 4);
#pragma unroll
    for (int u = 0; u < 2; ++u) {
        int f = tx + 256 * u;
        int row = f >> 5, col4 = (f & 31) * 4;
        cp_async16((u32)__cvta_generic_to_shared(&Bs[0][row][col4]),
                   Bg + (size_t)row * LDB + n0 + col4);
    }
    cp_commit();
    As[0][a_k8 + 0][a_row] = av0.x; As[0][a_k8 + 1][a_row] = av0.y;
    As[0][a_k8 + 2][a_row] = av0.z; As[0][a_k8 + 3][a_row] = av0.w;
    As[0][a_k8 + 4][a_row] = av1.x; As[0][a_k8 + 5][a_row] = av1.y;
    As[0][a_k8 + 6][a_row] = av1.z; As[0][a_k8 + 7][a_row] = av1.w;
    cp_wait0();
    __syncthreads();

    int s = 0;
    for (int k0 = 0; k0 < K; k0 += 16) {
        const bool has_next = (k0 + 16) < K;
        if (has_next) {
            av0 = *(const float4*)(A + (size_t)(m0 + a_row) * K + k0 + 16 + a_k8);
            av1 = *(const float4*)(A + (size_t)(m0 + a_row) * K + k0 + 16 + a_k8 + 4);
#pragma unroll
            for (int u = 0; u < 2; ++u) {
                int f = tx + 256 * u;
                int row = f >> 5, col4 = (f & 31) * 4;
                cp_async16((u32)__cvta_generic_to_shared(&Bs[s ^ 1][row][col4]),
                           Bg + (size_t)(k0 + 16 + row) * LDB + n0 + col4);
            }
            cp_commit();
        }

#pragma unroll
        for (int kk = 0; kk < 16; ++kk) {
            float4 a0 = *(const float4*)&As[s][kk][mreg];
            float4 a1 = *(const float4*)&As[s][kk][mreg + 4];
            ulonglong2 b0 = *(const ulonglong2*)&Bs[s][kk][nreg];
            ulonglong2 b1 = *(const ulonglong2*)&Bs[s][kk][nreg + 4];
            u64 bp[4] = {b0.x, b0.y, b1.x, b1.y};
            float ar[8] = {a0.x, a0.y, a0.z, a0.w, a1.x, a1.y, a1.z, a1.w};
#pragma unroll
            for (int i = 0; i < 8; ++i) {
                u64 ap = pk(ar[i], ar[i]);
#pragma unroll
                for (int j = 0; j < 4; ++j)
                    R.acc[i][j] = ffma2(ap, bp[j], R.acc[i][j]);
            }
        }

        if (has_next) {
            As[s^1][a_k8 + 0][a_row] = av0.x; As[s^1][a_k8 + 1][a_row] = av0.y;
            As[s^1][a_k8 + 2][a_row] = av0.z; As[s^1][a_k8 + 3][a_row] = av0.w;
            As[s^1][a_k8 + 4][a_row] = av1.x; As[s^1][a_k8 + 5][a_row] = av1.y;
            As[s^1][a_k8 + 6][a_row] = av1.z; As[s^1][a_k8 + 7][a_row] = av1.w;
        }
        cp_wait0();
        __syncthreads();
        s ^= 1;
    }
}

// ============================================================================
// QKV GEMM + scatter to [b,h,s,hd]
// ============================================================================
__global__ __launch_bounds__(256) void qkv_gemm(const float* __restrict__ x,
                                                const float* __restrict__ w,
                                                const float* __restrict__ bias)
{
    __shared__ float As[2][16][128];
    __shared__ float Bs[2][16][128];

    const int tx = threadIdx.x;
    const int m0 = blockIdx.y * 128;
    const int n0 = blockIdx.x * 128;
    const int mreg = (tx >> 4) * 8;
    const int nreg = (tx & 15) * 8;

    GemmAcc R;
    gemm_mainloop<N3>(x, w, m0, n0, DM, As, Bs, R);

#pragma unroll
    for (int i = 0; i < 8; ++i) {
        const int m = m0 + mreg + i;
        const int b = m >> 11;
        const int sI = m & 2047;
#pragma unroll
        for (int jp = 0; jp < 4; ++jp) {
            float c0, c1; upk(R.acc[i][jp], c0, c1);
            const int n = n0 + nreg + jp * 2;
#pragma unroll
            for (int q = 0; q < 2; ++q) {
                const int nn_full = n + q;
                const float v = (q ? c1 : c0) + bias[nn_full];
                const int seg = nn_full >> 10;
                const int nn  = nn_full & 1023;
                const int h   = nn >> 6;
                const int dd  = nn & 63;
                const size_t idx = ((((size_t)b * NH + h) * SQ + sI) << 6) + dd;
                if (seg == 0)      g_q[idx] = v;
                else if (seg == 1) g_k[idx] = v;
                else               g_v[idx] = v;
            }
        }
    }
}

// ============================================================================
// Output projection
// ============================================================================
__global__ __launch_bounds__(256) void proj_gemm(const float* __restrict__ w,
                                                 const float* __restrict__ bias,
                                                 float* __restrict__ out)
{
    __shared__ float As[2][16][128];
    __shared__ float Bs[2][16][128];

    const int tx = threadIdx.x;
    const int m0 = blockIdx.y * 128;
    const int n0 = blockIdx.x * 128;
    const int mreg = (tx >> 4) * 8;
    const int nreg = (tx & 15) * 8;

    GemmAcc R;
    gemm_mainloop<DM>(g_att, w, m0, n0, DM, As, Bs, R);

#pragma unroll
    for (int i = 0; i < 8; ++i) {
        const int m = m0 + mreg + i;
#pragma unroll
        for (int jh = 0; jh < 2; ++jh) {
            float c0, c1, c2, c3;
            upk(R.acc[i][jh * 2 + 0], c0, c1);
            upk(R.acc[i][jh * 2 + 1], c2, c3);
            const int n = n0 + nreg + jh * 4;
            float4 o = make_float4(c0 + bias[n], c1 + bias[n + 1],
                                   c2 + bias[n + 2], c3 + bias[n + 3]);
            *(float4*)(out + (size_t)m * DM + n) = o;
        }
    }
}

// ============================================================================
// Flash attention (fp32 packed, causal). Same structure as R1, f32x2 inner.
// ============================================================================
__global__ __launch_bounds__(256) void attn_kernel()
{
    extern __shared__ float sm[];
    float* Qs  = sm;              // [qrow][kd]
    float* KsT = sm + 4096;       // [kd][krow]
    float* Vs  = sm + 8192;       // [krow][hd]
    float* Ps  = sm + 12288;      // [qrow][krow]

    const int bh = blockIdx.y;
    const int qt = blockIdx.x;
    const int q0 = qt * 64;
    const float* Qg = g_q + (size_t)bh * SQ * HD;
    const float* Kg = g_k + (size_t)bh * SQ * HD;
    const float* Vg = g_v + (size_t)bh * SQ * HD;

    const int tx  = threadIdx.x;
    const int ty  = tx >> 4;
    const int tix = tx & 15;

    for (int i = tx; i < 1024; i += 256) {
        const int r = i >> 4, c4 = (i & 15) << 2;
        float4 v = *(const float4*)(Qg + (size_t)(q0 + r) * HD + c4);
        v.x *= 0.125f; v.y *= 0.125f; v.z *= 0.125f; v.w *= 0.125f;
        *(float4*)(Qs + r * HD + c4) = v;
    }

    u64 op[4][2];
#pragma unroll
    for (int i = 0; i < 4; ++i) { op[i][0] = 0ull; op[i][1] = 0ull; }
    float mrow[4] = {-1e30f, -1e30f, -1e30f, -1e30f};
    float lrow[4] = {0.f, 0.f, 0.f, 0.f};

    for (int kt = 0; kt <= qt; ++kt) {
        const int k0 = kt * 64;
        __syncthreads();

        for (int i = tx; i < 1024; i += 256) {
            const int r = i >> 4, c4 = (i & 15) << 2;
            float4 kv = *(const float4*)(Kg + (size_t)(k0 + r) * HD + c4);
            KsT[(c4 + 0) * 64 + r] = kv.x;
            KsT[(c4 + 1) * 64 + r] = kv.y;
            KsT[(c4 + 2) * 64 + r] = kv.z;
            KsT[(c4 + 3) * 64 + r] = kv.w;
            *(float4*)(Vs + r * HD + c4) =
                *(const float4*)(Vg + (size_t)(k0 + r) * HD + c4);
        }
        __syncthreads();

        // ---- scores (packed pairs over k-columns)
        u64 scp[4][2];
#pragma unroll
        for (int i = 0; i < 4; ++i) { scp[i][0] = 0ull; scp[i][1] = 0ull; }

#pragma unroll 4
        for (int kd = 0; kd < 64; kd += 4) {
            float qv[4][4];
#pragma unroll
            for (int i = 0; i < 4; ++i) {
                float4 t = *(const float4*)(Qs + (ty * 4 + i) * HD + kd);
                qv[i][0] = t.x; qv[i][1] = t.y; qv[i][2] = t.z; qv[i][3] = t.w;
            }
#pragma unroll
            for (int kk = 0; kk < 4; ++kk) {
                ulonglong2 kvp = *(const ulonglong2*)(KsT + (kd + kk) * 64 + tix * 4);
#pragma unroll
                for (int i = 0; i < 4; ++i) {
                    u64 ap = pk(qv[i][kk], qv[i][kk]);
                    scp[i][0] = ffma2(ap, kvp.x, scp[i][0]);
                    scp[i][1] = ffma2(ap, kvp.y, scp[i][1]);
                }
            }
        }

        float sc[4][4];
#pragma unroll
        for (int i = 0; i < 4; ++i) {
            upk(scp[i][0], sc[i][0], sc[i][1]);
            upk(scp[i][1], sc[i][2], sc[i][3]);
        }

        if (kt == qt) {
#pragma unroll
            for (int i = 0; i < 4; ++i)
#pragma unroll
                for (int j = 0; j < 4; ++j)
                    if (tix * 4 + j > ty * 4 + i) sc[i][j] = -1e30f;
        }

        // ---- online softmax
        float mt[4], scale[4], psum[4];
#pragma unroll
        for (int i = 0; i < 4; ++i)
            mt[i] = fmaxf(fmaxf(sc[i][0], sc[i][1]), fmaxf(sc[i][2], sc[i][3]));
#pragma unroll
        for (int off = 1; off < 16; off <<= 1)
#pragma unroll
            for (int i = 0; i < 4; ++i)
                mt[i] = fmaxf(mt[i], __shfl_xor_sync(0xffffffffu, mt[i], off));
#pragma unroll
        for (int i = 0; i < 4; ++i) {
            const float mnew = fmaxf(mrow[i], mt[i]);
            scale[i] = __expf(mrow[i] - mnew);
            mrow[i]  = mnew;
            psum[i]  = 0.f;
#pragma unroll
            for (int j = 0; j < 4; ++j) {
                const float p = __expf(sc[i][j] - mnew);
                sc[i][j] = p;
                psum[i] += p;
            }
        }
#pragma unroll
        for (int off = 1; off < 16; off <<= 1)
#pragma unroll
            for (int i = 0; i < 4; ++i)
                psum[i] += __shfl_xor_sync(0xffffffffu, psum[i], off);
#pragma unroll
        for (int i = 0; i < 4; ++i) {
            lrow[i] = lrow[i] * scale[i] + psum[i];
            u64 sp = pk(scale[i], scale[i]);
            op[i][0] = fmul2(op[i][0], sp);
            op[i][1] = fmul2(op[i][1], sp);
            *(float4*)(Ps + (ty * 4 + i) * 64 + tix * 4) =
                make_float4(sc[i][0], sc[i][1], sc[i][2], sc[i][3]);
        }
        __syncthreads();

        // ---- O += P @ V (packed)
#pragma unroll 4
        for (int j2 = 0; j2 < 64; j2 += 4) {
            float pv[4][4];
#pragma unroll
            for (int i = 0; i < 4; ++i) {
                float4 t = *(const float4*)(Ps + (ty * 4 + i) * 64 + j2);
                pv[i][0] = t.x; pv[i][1] = t.y; pv[i][2] = t.z; pv[i][3] = t.w;
            }
#pragma unroll
            for (int kk = 0; kk < 4; ++kk) {
                ulonglong2 vv = *(const ulonglong2*)(Vs + (j2 + kk) * HD + tix * 4);
#pragma unroll
                for (int i = 0; i < 4; ++i) {
                    u64 ap = pk(pv[i][kk], pv[i][kk]);
                    op[i][0] = ffma2(ap, vv.x, op[i][0]);
                    op[i][1] = ffma2(ap, vv.y, op[i][1]);
                }
            }
        }
    }

    const int b = bh >> 4, h = bh & 15;
#pragma unroll
    for (int i = 0; i < 4; ++i) {
        const float inv = 1.0f / lrow[i];
        float o0, o1, o2, o3;
        upk(op[i][0], o0, o1);
        upk(op[i][1], o2, o3);
        float4 o = make_float4(o0 * inv, o1 * inv, o2 * inv, o3 * inv);
        *(float4*)(g_att + ((size_t)b * SQ + q0 + ty * 4 + i) * DM
                   + h * 64 + tix * 4) = o;
    }
}

// ============================================================================
extern "C" void kernel_launch(void* const* d_in, const int* in_sizes, int n_in,
                              void* d_out, int out_size)
{
    const float* x    = (const float*)d_in[0];
    const float* attw = (const float*)d_in[1];
    const float* attb = (const float*)d_in[2];
    const float* pw   = (const float*)d_in[3];
    const float* pb   = (const float*)d_in[4];
    float* out = (float*)d_out;

    cudaFuncSetAttribute(attn_kernel,
                         cudaFuncAttributeMaxDynamicSharedMemorySize, 65536);

    qkv_gemm<<<dim3(N3 / 128, BS / 128), 256>>>(x, attw, attb);
    attn_kernel<<<dim3(SQ / 64, BB * NH), 256, 65536>>>();
    proj_gemm<<<dim3(DM / 128, BS / 128), 256>>>(pw, pb, out);
}

// round 5
// speedup vs baseline: 1.7975x; 1.5781x over previous
#include <cuda_runtime.h>
#include <cuda_bf16.h>
#include <cstdint>

#define BB   4
#define SQ   2048
#define DM   1024
#define NH   16
#define HD   64
#define BS   (BB*SQ)      // 8192
#define N3   (3*DM)       // 3072

typedef unsigned long long u64;
typedef unsigned int u32;

// ---------------- scratch (device globals; no allocation allowed) -----------
__device__ float g_q[(size_t)BB*NH*SQ*HD];
__device__ float g_k[(size_t)BB*NH*SQ*HD];
__device__ float g_v[(size_t)BB*NH*SQ*HD];
__device__ float g_att[(size_t)BS*DM];

__device__ __align__(16) __nv_bfloat16 g_ahi[(size_t)BS*DM];
__device__ __align__(16) __nv_bfloat16 g_alo[(size_t)BS*DM];
__device__ __align__(16) __nv_bfloat16 g_bhi[(size_t)N3*DM];   // attw^T [3072][1024]
__device__ __align__(16) __nv_bfloat16 g_blo[(size_t)N3*DM];
__device__ __align__(16) __nv_bfloat16 g_phi[(size_t)DM*DM];   // pw^T [1024][1024]
__device__ __align__(16) __nv_bfloat16 g_plo[(size_t)DM*DM];

// ---------------- packed fp32 helpers (attention) ----------------------------
__device__ __forceinline__ u64 pk(float a, float b) {
    u64 r; asm("mov.b64 %0, {%1, %2};" : "=l"(r) : "f"(a), "f"(b)); return r;
}
__device__ __forceinline__ void upk(u64 v, float& a, float& b) {
    asm("mov.b64 {%0, %1}, %2;" : "=f"(a), "=f"(b) : "l"(v));
}
__device__ __forceinline__ u64 ffma2(u64 a, u64 b, u64 c) {
    u64 d; asm("fma.rn.f32x2 %0, %1, %2, %3;" : "=l"(d) : "l"(a), "l"(b), "l"(c));
    return d;
}
__device__ __forceinline__ u64 fmul2(u64 a, u64 b) {
    u64 d; asm("mul.rn.f32x2 %0, %1, %2;" : "=l"(d) : "l"(a), "l"(b));
    return d;
}

// ---------------- async copy helpers -----------------------------------------
__device__ __forceinline__ void cp_async16(u32 smem, const void* g) {
    asm volatile("cp.async.cg.shared.global [%0], [%1], 16;" :: "r"(smem), "l"(g));
}
__device__ __forceinline__ void cp_commit()  { asm volatile("cp.async.commit_group;"); }
__device__ __forceinline__ void cp_wait0()   { asm volatile("cp.async.wait_group 0;"); }
__device__ __forceinline__ void cp_wait1()   { asm volatile("cp.async.wait_group 1;"); }

__device__ __forceinline__ u32 smem_u32(const void* p) {
    return (u32)__cvta_generic_to_shared(p);
}

// ---------------- mma.sync helpers (sm_80+ baseline features) -----------------
__device__ __forceinline__ void ldsm4(u32& r0, u32& r1, u32& r2, u32& r3, u32 a) {
    asm volatile("ldmatrix.sync.aligned.m8n8.x4.shared.b16 {%0,%1,%2,%3}, [%4];"
                 : "=r"(r0), "=r"(r1), "=r"(r2), "=r"(r3) : "r"(a));
}
__device__ __forceinline__ void ldsm2(u32& r0, u32& r1, u32 a) {
    asm volatile("ldmatrix.sync.aligned.m8n8.x2.shared.b16 {%0,%1}, [%2];"
                 : "=r"(r0), "=r"(r1) : "r"(a));
}
__device__ __forceinline__ void mma16816(float* d, const u32* a, const u32* b) {
    asm volatile(
        "mma.sync.aligned.m16n8k16.row.col.f32.bf16.bf16.f32 "
        "{%0,%1,%2,%3}, {%4,%5,%6,%7}, {%8,%9}, {%0,%1,%2,%3};"
        : "+f"(d[0]), "+f"(d[1]), "+f"(d[2]), "+f"(d[3])
        : "r"(a[0]), "r"(a[1]), "r"(a[2]), "r"(a[3]), "r"(b[0]), "r"(b[1]));
}

// ============================================================================
// Split / transpose-split conversion kernels (bf16 hi/lo)
// ============================================================================
template<int SRC_ATT>
__global__ __launch_bounds__(256) void conv_split(const float* __restrict__ in, int n4)
{
    const float* src = SRC_ATT ? g_att : in;
    int i = blockIdx.x * 256 + threadIdx.x;
    if (i >= n4) return;
    float4 v = ((const float4*)src)[i];
    __nv_bfloat16 h0 = __float2bfloat16(v.x);
    __nv_bfloat16 h1 = __float2bfloat16(v.y);
    __nv_bfloat16 h2 = __float2bfloat16(v.z);
    __nv_bfloat16 h3 = __float2bfloat16(v.w);
    __nv_bfloat16 l0 = __float2bfloat16(v.x - __bfloat162float(h0));
    __nv_bfloat16 l1 = __float2bfloat16(v.y - __bfloat162float(h1));
    __nv_bfloat16 l2 = __float2bfloat16(v.z - __bfloat162float(h2));
    __nv_bfloat16 l3 = __float2bfloat16(v.w - __bfloat162float(h3));
    ((__nv_bfloat162*)g_ahi)[i*2]   = __halves2bfloat162(h0, h1);
    ((__nv_bfloat162*)g_ahi)[i*2+1] = __halves2bfloat162(h2, h3);
    ((__nv_bfloat162*)g_alo)[i*2]   = __halves2bfloat162(l0, l1);
    ((__nv_bfloat162*)g_alo)[i*2+1] = __halves2bfloat162(l2, l3);
}

template<int WSEL>    // 0 -> g_bhi/g_blo (attn weight), 1 -> g_phi/g_plo (proj)
__global__ __launch_bounds__(256) void conv_transpose(const float* __restrict__ w,
                                                      int K, int N)
{
    __nv_bfloat16* hi = WSEL ? g_phi : g_bhi;
    __nv_bfloat16* lo = WSEL ? g_plo : g_blo;
    __shared__ float t[32][33];
    const int n0 = blockIdx.x * 32, k0 = blockIdx.y * 32;
    const int x = threadIdx.x & 31, y = (threadIdx.x >> 5) * 4;
#pragma unroll
    for (int r = 0; r < 4; ++r)
        t[y + r][x] = w[(size_t)(k0 + y + r) * N + n0 + x];
    __syncthreads();
#pragma unroll
    for (int r = 0; r < 4; ++r) {
        const int n = n0 + y + r, kk = k0 + x;
        const float f = t[x][y + r];
        __nv_bfloat16 h = __float2bfloat16(f);
        hi[(size_t)n * K + kk] = h;
        lo[(size_t)n * K + kk] = __float2bfloat16(f - __bfloat162float(h));
    }
}

// ============================================================================
// bf16x3 GEMM via mma.sync m16n8k16. 128x128 CTA tile, 8 warps (64x32 each),
// BK=64 double-buffered cp.async stages, XOR-swizzled smem for ldmatrix.
// MODE 0: qkv scatter (+bias). MODE 1: proj out (+bias).
// Stage layout: 4 tiles [Ahi, Alo, Bhi, Blo], each 128 rows x 128 bytes.
// ============================================================================
template<int MODE>
__global__ __launch_bounds__(256) void mma_gemm(const float* __restrict__ bias,
                                                float* __restrict__ outp)
{
    extern __shared__ char smem[];
    const u32 sb = smem_u32(smem);
    const int tx = threadIdx.x, wid = tx >> 5, lane = tx & 31;
    const int m0 = blockIdx.y * 128, n0 = blockIdx.x * 128;
    const int K = DM;
    const int NCH = K / 64;                 // 16 chunks

    const __nv_bfloat16* Ahi = g_ahi;
    const __nv_bfloat16* Alo = g_alo;
    const __nv_bfloat16* Bhi = MODE ? g_phi : g_bhi;
    const __nv_bfloat16* Blo = MODE ? g_plo : g_blo;

    const int wm = (wid & 1) * 64;          // warp m-offset in CTA tile
    const int wn = (wid >> 1) * 32;         // warp n-offset

    // swizzled byte offset within a tile: row r (0..127), 16B chunk c (0..7)
    auto swz = [](int r, int c) -> u32 {
        return (u32)(r * 128 + ((c ^ (r & 7)) * 16));
    };

    auto load_chunk = [&](int ci, int stage) {
        const int k0 = ci * 64;
#pragma unroll
        for (int t = 0; t < 4; ++t) {
            const __nv_bfloat16* src = (t == 0) ? Ahi : (t == 1) ? Alo
                                     : (t == 2) ? Bhi : Blo;
            const int rbase = (t < 2) ? m0 : n0;
            const u32 tb = sb + (u32)(stage * 65536 + t * 16384);
#pragma unroll
            for (int u = 0; u < 4; ++u) {
                const int id = tx + 256 * u;
                const int r = id >> 3, c = id & 7;
                cp_async16(tb + swz(r, c),
                           src + (size_t)(rbase + r) * K + k0 + c * 8);
            }
        }
        cp_commit();
    };

    float acc[4][4][4];
#pragma unroll
    for (int mt = 0; mt < 4; ++mt)
#pragma unroll
        for (int nt = 0; nt < 4; ++nt)
#pragma unroll
            for (int e = 0; e < 4; ++e) acc[mt][nt][e] = 0.f;

    load_chunk(0, 0);
    load_chunk(1, 1);

    // per-lane ldmatrix row/chunk components
    const int a_lrow = (lane & 7) + ((lane >> 3) & 1) * 8;   // 0..15
    const int a_lc   = (lane >> 4);                           // 0/1
    const int b_lrow = lane & 7;
    const int b_lc   = (lane >> 3) & 1;

    for (int i = 0; i < NCH; ++i) {
        const int s = i & 1;
        if (i + 1 < NCH) cp_wait1(); else cp_wait0();
        __syncthreads();

        const u32 tAhi = sb + (u32)(s * 65536);
        const u32 tAlo = tAhi + 16384;
        const u32 tBhi = tAhi + 32768;
        const u32 tBlo = tAhi + 49152;

#pragma unroll
        for (int ks = 0; ks < 4; ++ks) {
            u32 ah[4][4], al[4][4];
#pragma unroll
            for (int mt = 0; mt < 4; ++mt) {
                const int row = wm + mt * 16 + a_lrow;
                const int c   = ks * 2 + a_lc;
                ldsm4(ah[mt][0], ah[mt][1], ah[mt][2], ah[mt][3], tAhi + swz(row, c));
                ldsm4(al[mt][0], al[mt][1], al[mt][2], al[mt][3], tAlo + swz(row, c));
            }
            u32 bh[4][2], bl[4][2];
#pragma unroll
            for (int nt = 0; nt < 4; ++nt) {
                const int row = wn + nt * 8 + b_lrow;
                const int c   = ks * 2 + b_lc;
                ldsm2(bh[nt][0], bh[nt][1], tBhi + swz(row, c));
                ldsm2(bl[nt][0], bl[nt][1], tBlo + swz(row, c));
            }
#pragma unroll
            for (int mt = 0; mt < 4; ++mt)
#pragma unroll
                for (int nt = 0; nt < 4; ++nt) {
                    mma16816(acc[mt][nt], ah[mt], bh[nt]);
                    mma16816(acc[mt][nt], ah[mt], bl[nt]);
                    mma16816(acc[mt][nt], al[mt], bh[nt]);
                }
        }

        __syncthreads();
        if (i + 2 < NCH) load_chunk(i + 2, s);
    }

    // ---- epilogue: register fragments -> global (float2 per store) ----------
    const int r_in  = lane >> 2;
    const int cpair = (lane & 3) * 2;

    if (MODE == 0) {
        const int seg = n0 >> 10;           // whole CTA lies in one of q/k/v
        float* dstbase = (seg == 0) ? g_q : (seg == 1) ? g_k : g_v;
#pragma unroll
        for (int mt = 0; mt < 4; ++mt)
#pragma unroll
            for (int nt = 0; nt < 4; ++nt)
#pragma unroll
                for (int hh = 0; hh < 2; ++hh) {
                    const int m = m0 + wm + mt * 16 + r_in + hh * 8;
                    const int n = n0 + wn + nt * 8 + cpair;
                    const int b  = m >> 11;
                    const int sI = m & 2047;
                    const int nn = n & 1023;
                    const int h  = nn >> 6, dd = nn & 63;
                    float2 v;
                    v.x = acc[mt][nt][hh * 2 + 0] + bias[n];
                    v.y = acc[mt][nt][hh * 2 + 1] + bias[n + 1];
                    const size_t idx = ((((size_t)b * NH + h) * SQ + sI) << 6) + dd;
                    *(float2*)(dstbase + idx) = v;
                }
    } else {
#pragma unroll
        for (int mt = 0; mt < 4; ++mt)
#pragma unroll
            for (int nt = 0; nt < 4; ++nt)
#pragma unroll
                for (int hh = 0; hh < 2; ++hh) {
                    const int m = m0 + wm + mt * 16 + r_in + hh * 8;
                    const int n = n0 + wn + nt * 8 + cpair;
                    float2 v;
                    v.x = acc[mt][nt][hh * 2 + 0] + bias[n];
                    v.y = acc[mt][nt][hh * 2 + 1] + bias[n + 1];
                    *(float2*)(outp + (size_t)m * DM + n) = v;
                }
    }
}

// ============================================================================
// Flash attention (fp32 packed, causal) — unchanged.
// ============================================================================
__global__ __launch_bounds__(256) void attn_kernel()
{
    extern __shared__ float sm[];
    float* Qs  = sm;
    float* KsT = sm + 4096;
    float* Vs  = sm + 8192;
    float* Ps  = sm + 12288;

    const int bh = blockIdx.y;
    const int qt = blockIdx.x;
    const int q0 = qt * 64;
    const float* Qg = g_q + (size_t)bh * SQ * HD;
    const float* Kg = g_k + (size_t)bh * SQ * HD;
    const float* Vg = g_v + (size_t)bh * SQ * HD;

    const int tx  = threadIdx.x;
    const int ty  = tx >> 4;
    const int tix = tx & 15;

    for (int i = tx; i < 1024; i += 256) {
        const int r = i >> 4, c4 = (i & 15) << 2;
        float4 v = *(const float4*)(Qg + (size_t)(q0 + r) * HD + c4);
        v.x *= 0.125f; v.y *= 0.125f; v.z *= 0.125f; v.w *= 0.125f;
        *(float4*)(Qs + r * HD + c4) = v;
    }

    u64 op[4][2];
#pragma unroll
    for (int i = 0; i < 4; ++i) { op[i][0] = 0ull; op[i][1] = 0ull; }
    float mrow[4] = {-1e30f, -1e30f, -1e30f, -1e30f};
    float lrow[4] = {0.f, 0.f, 0.f, 0.f};

    for (int kt = 0; kt <= qt; ++kt) {
        const int k0 = kt * 64;
        __syncthreads();

        for (int i = tx; i < 1024; i += 256) {
            const int r = i >> 4, c4 = (i & 15) << 2;
            float4 kv = *(const float4*)(Kg + (size_t)(k0 + r) * HD + c4);
            KsT[(c4 + 0) * 64 + r] = kv.x;
            KsT[(c4 + 1) * 64 + r] = kv.y;
            KsT[(c4 + 2) * 64 + r] = kv.z;
            KsT[(c4 + 3) * 64 + r] = kv.w;
            *(float4*)(Vs + r * HD + c4) =
                *(const float4*)(Vg + (size_t)(k0 + r) * HD + c4);
        }
        __syncthreads();

        u64 scp[4][2];
#pragma unroll
        for (int i = 0; i < 4; ++i) { scp[i][0] = 0ull; scp[i][1] = 0ull; }

#pragma unroll 4
        for (int kd = 0; kd < 64; kd += 4) {
            float qv[4][4];
#pragma unroll
            for (int i = 0; i < 4; ++i) {
                float4 t = *(const float4*)(Qs + (ty * 4 + i) * HD + kd);
                qv[i][0] = t.x; qv[i][1] = t.y; qv[i][2] = t.z; qv[i][3] = t.w;
            }
#pragma unroll
            for (int kk = 0; kk < 4; ++kk) {
                ulonglong2 kvp = *(const ulonglong2*)(KsT + (kd + kk) * 64 + tix * 4);
#pragma unroll
                for (int i = 0; i < 4; ++i) {
                    u64 ap = pk(qv[i][kk], qv[i][kk]);
                    scp[i][0] = ffma2(ap, kvp.x, scp[i][0]);
                    scp[i][1] = ffma2(ap, kvp.y, scp[i][1]);
                }
            }
        }

        float sc[4][4];
#pragma unroll
        for (int i = 0; i < 4; ++i) {
            upk(scp[i][0], sc[i][0], sc[i][1]);
            upk(scp[i][1], sc[i][2], sc[i][3]);
        }

        if (kt == qt) {
#pragma unroll
            for (int i = 0; i < 4; ++i)
#pragma unroll
                for (int j = 0; j < 4; ++j)
                    if (tix * 4 + j > ty * 4 + i) sc[i][j] = -1e30f;
        }

        float mt[4], scale[4], psum[4];
#pragma unroll
        for (int i = 0; i < 4; ++i)
            mt[i] = fmaxf(fmaxf(sc[i][0], sc[i][1]), fmaxf(sc[i][2], sc[i][3]));
#pragma unroll
        for (int off = 1; off < 16; off <<= 1)
#pragma unroll
            for (int i = 0; i < 4; ++i)
                mt[i] = fmaxf(mt[i], __shfl_xor_sync(0xffffffffu, mt[i], off));
#pragma unroll
        for (int i = 0; i < 4; ++i) {
            const float mnew = fmaxf(mrow[i], mt[i]);
            scale[i] = __expf(mrow[i] - mnew);
            mrow[i]  = mnew;
            psum[i]  = 0.f;
#pragma unroll
            for (int j = 0; j < 4; ++j) {
                const float p = __expf(sc[i][j] - mnew);
                sc[i][j] = p;
                psum[i] += p;
            }
        }
#pragma unroll
        for (int off = 1; off < 16; off <<= 1)
#pragma unroll
            for (int i = 0; i < 4; ++i)
                psum[i] += __shfl_xor_sync(0xffffffffu, psum[i], off);
#pragma unroll
        for (int i = 0; i < 4; ++i) {
            lrow[i] = lrow[i] * scale[i] + psum[i];
            u64 sp = pk(scale[i], scale[i]);
            op[i][0] = fmul2(op[i][0], sp);
            op[i][1] = fmul2(op[i][1], sp);
            *(float4*)(Ps + (ty * 4 + i) * 64 + tix * 4) =
                make_float4(sc[i][0], sc[i][1], sc[i][2], sc[i][3]);
        }
        __syncthreads();

#pragma unroll 4
        for (int j2 = 0; j2 < 64; j2 += 4) {
            float pv[4][4];
#pragma unroll
            for (int i = 0; i < 4; ++i) {
                float4 t = *(const float4*)(Ps + (ty * 4 + i) * 64 + j2);
                pv[i][0] = t.x; pv[i][1] = t.y; pv[i][2] = t.z; pv[i][3] = t.w;
            }
#pragma unroll
            for (int kk = 0; kk < 4; ++kk) {
                ulonglong2 vv = *(const ulonglong2*)(Vs + (j2 + kk) * HD + tix * 4);
#pragma unroll
                for (int i = 0; i < 4; ++i) {
                    u64 ap = pk(pv[i][kk], pv[i][kk]);
                    op[i][0] = ffma2(ap, vv.x, op[i][0]);
                    op[i][1] = ffma2(ap, vv.y, op[i][1]);
                }
            }
        }
    }

    const int b = bh >> 4, h = bh & 15;
#pragma unroll
    for (int i = 0; i < 4; ++i) {
        const float inv = 1.0f / lrow[i];
        float o0, o1, o2, o3;
        upk(op[i][0], o0, o1);
        upk(op[i][1], o2, o3);
        float4 o = make_float4(o0 * inv, o1 * inv, o2 * inv, o3 * inv);
        *(float4*)(g_att + ((size_t)b * SQ + q0 + ty * 4 + i) * DM
                   + h * 64 + tix * 4) = o;
    }
}

// ============================================================================
extern "C" void kernel_launch(void* const* d_in, const int* in_sizes, int n_in,
                              void* d_out, int out_size)
{
    const float* x    = (const float*)d_in[0];
    const float* attw = (const float*)d_in[1];
    const float* attb = (const float*)d_in[2];
    const float* pw   = (const float*)d_in[3];
    const float* pb   = (const float*)d_in[4];
    float* out = (float*)d_out;

    const int MMA_SMEM = 2 * 65536;   // 131072
    cudaFuncSetAttribute(mma_gemm<0>,
        cudaFuncAttributeMaxDynamicSharedMemorySize, MMA_SMEM);
    cudaFuncSetAttribute(mma_gemm<1>,
        cudaFuncAttributeMaxDynamicSharedMemorySize, MMA_SMEM);
    cudaFuncSetAttribute(attn_kernel,
        cudaFuncAttributeMaxDynamicSharedMemorySize, 65536);

    const int n4 = BS * DM / 4;

    conv_split<0><<<(n4 + 255) / 256, 256>>>(x, n4);
    conv_transpose<0><<<dim3(N3 / 32, DM / 32), 256>>>(attw, DM, N3);
    conv_transpose<1><<<dim3(DM / 32, DM / 32), 256>>>(pw, DM, DM);

    mma_gemm<0><<<dim3(N3 / 128, BS / 128), 256, MMA_SMEM>>>(attb, nullptr);

    attn_kernel<<<dim3(SQ / 64, BB * NH), 256, 65536>>>();

    conv_split<1><<<(n4 + 255) / 256, 256>>>(nullptr, n4);
    mma_gemm<1><<<dim3(DM / 128, BS / 128), 256, MMA_SMEM>>>(pb, out);
}

// round 6
// speedup vs baseline: 3.3227x; 1.8485x over previous
#include <cuda_runtime.h>
#include <cuda_bf16.h>
#include <cstdint>

#define BB   4
#define SQ   2048
#define DM   1024
#define NH   16
#define HD   64
#define BS   (BB*SQ)      // 8192
#define N3   (3*DM)       // 3072

typedef unsigned long long u64;
typedef unsigned int u32;
typedef __nv_bfloat16 bf16;
typedef __nv_bfloat162 bf162;

// Q pre-scale: 1/sqrt(64) * log2(e)  (softmax done in base-2 domain)
#define QSCALE 0.1803368801111204f

// ---------------- scratch (device globals; no allocation allowed) -----------
__device__ __align__(16) bf16 g_qhi[(size_t)BB*NH*SQ*HD];
__device__ __align__(16) bf16 g_qlo[(size_t)BB*NH*SQ*HD];
__device__ __align__(16) bf16 g_khi[(size_t)BB*NH*SQ*HD];
__device__ __align__(16) bf16 g_klo[(size_t)BB*NH*SQ*HD];
__device__ __align__(16) bf16 g_vhi[(size_t)BB*NH*SQ*HD];
__device__ __align__(16) bf16 g_vlo[(size_t)BB*NH*SQ*HD];

__device__ __align__(16) bf16 g_ahi[(size_t)BS*DM];
__device__ __align__(16) bf16 g_alo[(size_t)BS*DM];
__device__ __align__(16) bf16 g_bhi[(size_t)N3*DM];   // attw^T [3072][1024]
__device__ __align__(16) bf16 g_blo[(size_t)N3*DM];
__device__ __align__(16) bf16 g_phi[(size_t)DM*DM];   // pw^T [1024][1024]
__device__ __align__(16) bf16 g_plo[(size_t)DM*DM];

// ---------------- helpers -----------------------------------------------------
__device__ __forceinline__ void cp_async16(u32 smem, const void* g) {
    asm volatile("cp.async.cg.shared.global [%0], [%1], 16;" :: "r"(smem), "l"(g));
}
__device__ __forceinline__ void cp_commit()  { asm volatile("cp.async.commit_group;"); }
__device__ __forceinline__ void cp_wait0()   { asm volatile("cp.async.wait_group 0;"); }
__device__ __forceinline__ void cp_wait1()   { asm volatile("cp.async.wait_group 1;"); }
__device__ __forceinline__ u32 smem_u32(const void* p) {
    return (u32)__cvta_generic_to_shared(p);
}
__device__ __forceinline__ float ex2(float x) {
    float y; asm("ex2.approx.f32 %0, %1;" : "=f"(y) : "f"(x)); return y;
}
__device__ __forceinline__ void ldsm4(u32& r0, u32& r1, u32& r2, u32& r3, u32 a) {
    asm volatile("ldmatrix.sync.aligned.m8n8.x4.shared.b16 {%0,%1,%2,%3}, [%4];"
                 : "=r"(r0), "=r"(r1), "=r"(r2), "=r"(r3) : "r"(a));
}
__device__ __forceinline__ void ldsm2(u32& r0, u32& r1, u32 a) {
    asm volatile("ldmatrix.sync.aligned.m8n8.x2.shared.b16 {%0,%1}, [%2];"
                 : "=r"(r0), "=r"(r1) : "r"(a));
}
__device__ __forceinline__ void ldsm2t(u32& r0, u32& r1, u32 a) {
    asm volatile("ldmatrix.sync.aligned.m8n8.x2.trans.shared.b16 {%0,%1}, [%2];"
                 : "=r"(r0), "=r"(r1) : "r"(a));
}
__device__ __forceinline__ void mma16816(float* d, const u32* a, const u32* b) {
    asm volatile(
        "mma.sync.aligned.m16n8k16.row.col.f32.bf16.bf16.f32 "
        "{%0,%1,%2,%3}, {%4,%5,%6,%7}, {%8,%9}, {%0,%1,%2,%3};"
        : "+f"(d[0]), "+f"(d[1]), "+f"(d[2]), "+f"(d[3])
        : "r"(a[0]), "r"(a[1]), "r"(a[2]), "r"(a[3]), "r"(b[0]), "r"(b[1]));
}
__device__ __forceinline__ u32 pkbf(float lo, float hi) {
    bf162 t = __halves2bfloat162(__float2bfloat16(lo), __float2bfloat16(hi));
    return *(u32*)&t;
}
// swizzled byte offset in a [rows x 128B] tile
__device__ __forceinline__ u32 swz(int r, int c) {
    return (u32)(r * 128 + ((c ^ (r & 7)) * 16));
}

// ============================================================================
// Conversion kernels
// ============================================================================
__global__ __launch_bounds__(256) void conv_split_x(const float* __restrict__ in, int n4)
{
    int i = blockIdx.x * 256 + threadIdx.x;
    if (i >= n4) return;
    float4 v = ((const float4*)in)[i];
    bf16 h0 = __float2bfloat16(v.x), h1 = __float2bfloat16(v.y);
    bf16 h2 = __float2bfloat16(v.z), h3 = __float2bfloat16(v.w);
    ((bf162*)g_ahi)[i*2]   = __halves2bfloat162(h0, h1);
    ((bf162*)g_ahi)[i*2+1] = __halves2bfloat162(h2, h3);
    ((bf162*)g_alo)[i*2]   = __halves2bfloat162(
        __float2bfloat16(v.x - __bfloat162float(h0)),
        __float2bfloat16(v.y - __bfloat162float(h1)));
    ((bf162*)g_alo)[i*2+1] = __halves2bfloat162(
        __float2bfloat16(v.z - __bfloat162float(h2)),
        __float2bfloat16(v.w - __bfloat162float(h3)));
}

template<int WSEL>    // 0 -> g_bhi/g_blo, 1 -> g_phi/g_plo
__global__ __launch_bounds__(256) void conv_transpose(const float* __restrict__ w,
                                                      int K, int N)
{
    bf16* hi = WSEL ? g_phi : g_bhi;
    bf16* lo = WSEL ? g_plo : g_blo;
    __shared__ float t[32][33];
    const int n0 = blockIdx.x * 32, k0 = blockIdx.y * 32;
    const int x = threadIdx.x & 31, y = (threadIdx.x >> 5) * 4;
#pragma unroll
    for (int r = 0; r < 4; ++r)
        t[y + r][x] = w[(size_t)(k0 + y + r) * N + n0 + x];
    __syncthreads();
#pragma unroll
    for (int r = 0; r < 4; ++r) {
        const int n = n0 + y + r, kk = k0 + x;
        const float f = t[x][y + r];
        bf16 h = __float2bfloat16(f);
        hi[(size_t)n * K + kk] = h;
        lo[(size_t)n * K + kk] = __float2bfloat16(f - __bfloat162float(h));
    }
}

// ============================================================================
// bf16x3 GEMM via mma.sync. 128x128 CTA, 8 warps (64x32), BK=64, 2 stages.
// MODE 0: qkv -> bf16 hi/lo scatter (Q pre-scaled).  MODE 1: proj -> out fp32.
// ============================================================================
template<int MODE>
__global__ __launch_bounds__(256) void mma_gemm(const float* __restrict__ bias,
                                                float* __restrict__ outp)
{
    extern __shared__ char smem[];
    const u32 sb = smem_u32(smem);
    const int tx = threadIdx.x, wid = tx >> 5, lane = tx & 31;
    const int m0 = blockIdx.y * 128, n0 = blockIdx.x * 128;
    const int K = DM;
    const int NCH = K / 64;

    const bf16* Ahi = g_ahi;
    const bf16* Alo = g_alo;
    const bf16* Bhi = MODE ? g_phi : g_bhi;
    const bf16* Blo = MODE ? g_plo : g_blo;

    const int wm = (wid & 1) * 64;
    const int wn = (wid >> 1) * 32;

    auto load_chunk = [&](int ci, int stage) {
        const int k0 = ci * 64;
#pragma unroll
        for (int t = 0; t < 4; ++t) {
            const bf16* src = (t == 0) ? Ahi : (t == 1) ? Alo
                            : (t == 2) ? Bhi : Blo;
            const int rbase = (t < 2) ? m0 : n0;
            const u32 tb = sb + (u32)(stage * 65536 + t * 16384);
#pragma unroll
            for (int u = 0; u < 4; ++u) {
                const int id = tx + 256 * u;
                const int r = id >> 3, c = id & 7;
                cp_async16(tb + swz(r, c),
                           src + (size_t)(rbase + r) * K + k0 + c * 8);
            }
        }
        cp_commit();
    };

    float acc[4][4][4];
#pragma unroll
    for (int mt = 0; mt < 4; ++mt)
#pragma unroll
        for (int nt = 0; nt < 4; ++nt)
#pragma unroll
            for (int e = 0; e < 4; ++e) acc[mt][nt][e] = 0.f;

    load_chunk(0, 0);
    load_chunk(1, 1);

    const int a_lrow = lane & 15;
    const int a_lc   = lane >> 4;
    const int b_lrow = lane & 7;
    const int b_lc   = (lane >> 3) & 1;

    for (int i = 0; i < NCH; ++i) {
        const int s = i & 1;
        if (i + 1 < NCH) cp_wait1(); else cp_wait0();
        __syncthreads();

        const u32 tAhi = sb + (u32)(s * 65536);
        const u32 tAlo = tAhi + 16384;
        const u32 tBhi = tAhi + 32768;
        const u32 tBlo = tAhi + 49152;

#pragma unroll
        for (int ks = 0; ks < 4; ++ks) {
            u32 ah[4][4], al[4][4];
#pragma unroll
            for (int mt = 0; mt < 4; ++mt) {
                const int row = wm + mt * 16 + a_lrow;
                const int c   = ks * 2 + a_lc;
                ldsm4(ah[mt][0], ah[mt][1], ah[mt][2], ah[mt][3], tAhi + swz(row, c));
                ldsm4(al[mt][0], al[mt][1], al[mt][2], al[mt][3], tAlo + swz(row, c));
            }
            u32 bh[4][2], bl[4][2];
#pragma unroll
            for (int nt = 0; nt < 4; ++nt) {
                const int row = wn + nt * 8 + b_lrow;
                const int c   = ks * 2 + b_lc;
                ldsm2(bh[nt][0], bh[nt][1], tBhi + swz(row, c));
                ldsm2(bl[nt][0], bl[nt][1], tBlo + swz(row, c));
            }
#pragma unroll
            for (int mt = 0; mt < 4; ++mt)
#pragma unroll
                for (int nt = 0; nt < 4; ++nt) {
                    mma16816(acc[mt][nt], ah[mt], bh[nt]);
                    mma16816(acc[mt][nt], ah[mt], bl[nt]);
                    mma16816(acc[mt][nt], al[mt], bh[nt]);
                }
        }

        __syncthreads();
        if (i + 2 < NCH) load_chunk(i + 2, s);
    }

    const int r_in  = lane >> 2;
    const int cpair = (lane & 3) * 2;

    if (MODE == 0) {
        const int seg = n0 >> 10;
        bf16 *dhi, *dlo;
        if (seg == 0)      { dhi = g_qhi; dlo = g_qlo; }
        else if (seg == 1) { dhi = g_khi; dlo = g_klo; }
        else               { dhi = g_vhi; dlo = g_vlo; }
        const float qs = (seg == 0) ? QSCALE : 1.0f;
#pragma unroll
        for (int mt = 0; mt < 4; ++mt)
#pragma unroll
            for (int nt = 0; nt < 4; ++nt)
#pragma unroll
                for (int hh = 0; hh < 2; ++hh) {
                    const int m = m0 + wm + mt * 16 + r_in + hh * 8;
                    const int n = n0 + wn + nt * 8 + cpair;
                    const int b  = m >> 11;
                    const int sI = m & 2047;
                    const int nn = n & 1023;
                    const int h  = nn >> 6, dd = nn & 63;
                    const float vx = (acc[mt][nt][hh*2+0] + bias[n]) * qs;
                    const float vy = (acc[mt][nt][hh*2+1] + bias[n+1]) * qs;
                    const bf16 hx = __float2bfloat16(vx);
                    const bf16 hy = __float2bfloat16(vy);
                    const size_t idx = ((((size_t)b * NH + h) * SQ + sI) << 6) + dd;
                    *(bf162*)(dhi + idx) = __halves2bfloat162(hx, hy);
                    *(bf162*)(dlo + idx) = __halves2bfloat162(
                        __float2bfloat16(vx - __bfloat162float(hx)),
                        __float2bfloat16(vy - __bfloat162float(hy)));
                }
    } else {
#pragma unroll
        for (int mt = 0; mt < 4; ++mt)
#pragma unroll
            for (int nt = 0; nt < 4; ++nt)
#pragma unroll
                for (int hh = 0; hh < 2; ++hh) {
                    const int m = m0 + wm + mt * 16 + r_in + hh * 8;
                    const int n = n0 + wn + nt * 8 + cpair;
                    float2 v;
                    v.x = acc[mt][nt][hh * 2 + 0] + bias[n];
                    v.y = acc[mt][nt][hh * 2 + 1] + bias[n + 1];
                    *(float2*)(outp + (size_t)m * DM + n) = v;
                }
    }
}

// ============================================================================
// Tensor-core flash attention. CTA = 128 q-rows x one (b,h). 8 warps, 16 rows
// each. K-chunks of 64 keys, double-buffered. bf16x3 split on both GEMMs.
// Scores are base-2 logits (Q pre-scaled by 1/8*log2e) -> ex2.approx softmax.
// Writes normalized output split hi/lo into g_ahi/g_alo (proj GEMM input).
// smem: Qhi 16K | Qlo 16K | 2 stages x {Khi,Klo,Vhi,Vlo} 8K each = 96 KB.
// ============================================================================
__global__ __launch_bounds__(256) void attn_mma()
{
    extern __shared__ char smem[];
    const u32 sb = smem_u32(smem);
    const int tx = threadIdx.x, wid = tx >> 5, lane = tx & 31;
    const int qt = blockIdx.x, bh = blockIdx.y;
    const int q0 = qt * 128;
    const int wm = wid * 16;
    const size_t base = (size_t)bh * SQ * HD;

    const bf16* Qh = g_qhi + base;
    const bf16* Ql = g_qlo + base;
    const bf16* Kh = g_khi + base;
    const bf16* Kl = g_klo + base;
    const bf16* Vh = g_vhi + base;
    const bf16* Vl = g_vlo + base;

    // ---- prologue loads: Q (both tiles) + chunk 0 in group 0; chunk 1 group 1
#pragma unroll
    for (int u = 0; u < 4; ++u) {
        const int id = tx + 256 * u;
        const int r = id >> 3, c = id & 7;
        cp_async16(sb + swz(r, c),         Qh + (size_t)(q0 + r) * HD + c * 8);
        cp_async16(sb + 16384 + swz(r, c), Ql + (size_t)(q0 + r) * HD + c * 8);
    }
    auto load_chunk = [&](int kt, int s) {
        const int k0 = kt * 64;
        const u32 st = sb + 32768 + (u32)s * 32768;
#pragma unroll
        for (int u = 0; u < 2; ++u) {
            const int id = tx + 256 * u;
            const int r = id >> 3, c = id & 7;
            cp_async16(st + swz(r, c),          Kh + (size_t)(k0 + r) * HD + c * 8);
            cp_async16(st + 8192 + swz(r, c),   Kl + (size_t)(k0 + r) * HD + c * 8);
            cp_async16(st + 16384 + swz(r, c),  Vh + (size_t)(k0 + r) * HD + c * 8);
            cp_async16(st + 24576 + swz(r, c),  Vl + (size_t)(k0 + r) * HD + c * 8);
        }
        cp_commit();
    };
    load_chunk(0, 0);
    const int NCH = 2 * qt + 2;
    load_chunk(1, 1);

    u32 qh[4][4], ql[4][4];
    bool qloaded = false;

    float O[8][4];
#pragma unroll
    for (int jn = 0; jn < 8; ++jn)
#pragma unroll
        for (int e = 0; e < 4; ++e) O[jn][e] = 0.f;
    float mrow[2] = {-1e30f, -1e30f};
    float lrow[2] = {0.f, 0.f};

    const int a_lrow = lane & 15;
    const int a_lc   = lane >> 4;
    const int b_lrow = lane & 7;
    const int b_lc   = (lane >> 3) & 1;

    for (int kt = 0; kt < NCH; ++kt) {
        const int s = kt & 1;
        const int k0 = kt * 64;
        if (kt + 1 < NCH) cp_wait1(); else cp_wait0();
        __syncthreads();

        if (!qloaded) {
            qloaded = true;
#pragma unroll
            for (int kt2 = 0; kt2 < 4; ++kt2) {
                const u32 a = swz(wm + a_lrow, kt2 * 2 + a_lc);
                ldsm4(qh[kt2][0], qh[kt2][1], qh[kt2][2], qh[kt2][3], sb + a);
                ldsm4(ql[kt2][0], ql[kt2][1], ql[kt2][2], ql[kt2][3], sb + 16384 + a);
            }
        }

        const bool active = (k0 <= q0 + wm + 15);   // warp has any unmasked key
        if (active) {
            const u32 stK = sb + 32768 + (u32)s * 32768;
            const u32 stKl = stK + 8192;
            const u32 stV = stK + 16384;
            const u32 stVl = stK + 24576;

            float S[8][4];
#pragma unroll
            for (int n = 0; n < 8; ++n)
#pragma unroll
                for (int e = 0; e < 4; ++e) S[n][e] = 0.f;

#pragma unroll
            for (int kt2 = 0; kt2 < 4; ++kt2) {
#pragma unroll
                for (int n = 0; n < 8; ++n) {
                    const u32 a = swz(n * 8 + b_lrow, kt2 * 2 + b_lc);
                    u32 kb[2], klb[2];
                    ldsm2(kb[0], kb[1], stK + a);
                    ldsm2(klb[0], klb[1], stKl + a);
                    mma16816(S[n], qh[kt2], kb);
                    mma16816(S[n], qh[kt2], klb);
                    mma16816(S[n], ql[kt2], kb);
                }
            }

            // causal mask (only chunks overlapping the diagonal)
            if (k0 + 63 > q0 + wm) {
                const int r0g = q0 + wm + (lane >> 2);
                const int cb  = k0 + (lane & 3) * 2;
#pragma unroll
                for (int n = 0; n < 8; ++n)
#pragma unroll
                    for (int e = 0; e < 2; ++e) {
                        const int col = cb + n * 8 + e;
                        if (col > r0g)     S[n][e]     = -1e30f;
                        if (col > r0g + 8) S[n][2 + e] = -1e30f;
                    }
            }

            // ---- online softmax (base-2)
            float m0n = mrow[0], m1n = mrow[1];
#pragma unroll
            for (int n = 0; n < 8; ++n) {
                m0n = fmaxf(m0n, fmaxf(S[n][0], S[n][1]));
                m1n = fmaxf(m1n, fmaxf(S[n][2], S[n][3]));
            }
            m0n = fmaxf(m0n, __shfl_xor_sync(0xffffffffu, m0n, 1));
            m0n = fmaxf(m0n, __shfl_xor_sync(0xffffffffu, m0n, 2));
            m1n = fmaxf(m1n, __shfl_xor_sync(0xffffffffu, m1n, 1));
            m1n = fmaxf(m1n, __shfl_xor_sync(0xffffffffu, m1n, 2));

            const float sc0 = ex2(mrow[0] - m0n);
            const float sc1 = ex2(mrow[1] - m1n);
            mrow[0] = m0n; mrow[1] = m1n;

            float ps0 = 0.f, ps1 = 0.f;
#pragma unroll
            for (int n = 0; n < 8; ++n) {
                S[n][0] = ex2(S[n][0] - m0n); ps0 += S[n][0];
                S[n][1] = ex2(S[n][1] - m0n); ps0 += S[n][1];
                S[n][2] = ex2(S[n][2] - m1n); ps1 += S[n][2];
                S[n][3] = ex2(S[n][3] - m1n); ps1 += S[n][3];
            }
            ps0 += __shfl_xor_sync(0xffffffffu, ps0, 1);
            ps0 += __shfl_xor_sync(0xffffffffu, ps0, 2);
            ps1 += __shfl_xor_sync(0xffffffffu, ps1, 1);
            ps1 += __shfl_xor_sync(0xffffffffu, ps1, 2);
            lrow[0] = lrow[0] * sc0 + ps0;
            lrow[1] = lrow[1] * sc1 + ps1;
#pragma unroll
            for (int jn = 0; jn < 8; ++jn) {
                O[jn][0] *= sc0; O[jn][1] *= sc0;
                O[jn][2] *= sc1; O[jn][3] *= sc1;
            }

            // ---- P @ V (split): P frags built directly from S registers
#pragma unroll
            for (int kt2 = 0; kt2 < 4; ++kt2) {
                u32 ph[4], pl[4];
                {
                    const int n0i = 2 * kt2, n1i = 2 * kt2 + 1;
                    float h00, h01, h10, h11, h20, h21, h30, h31;
                    ph[0] = pkbf(S[n0i][0], S[n0i][1]);
                    ph[1] = pkbf(S[n0i][2], S[n0i][3]);
                    ph[2] = pkbf(S[n1i][0], S[n1i][1]);
                    ph[3] = pkbf(S[n1i][2], S[n1i][3]);
                    h00 = __bfloat162float(__float2bfloat16(S[n0i][0]));
                    h01 = __bfloat162float(__float2bfloat16(S[n0i][1]));
                    h10 = __bfloat162float(__float2bfloat16(S[n0i][2]));
                    h11 = __bfloat162float(__float2bfloat16(S[n0i][3]));
                    h20 = __bfloat162float(__float2bfloat16(S[n1i][0]));
                    h21 = __bfloat162float(__float2bfloat16(S[n1i][1]));
                    h30 = __bfloat162float(__float2bfloat16(S[n1i][2]));
                    h31 = __bfloat162float(__float2bfloat16(S[n1i][3]));
                    pl[0] = pkbf(S[n0i][0] - h00, S[n0i][1] - h01);
                    pl[1] = pkbf(S[n0i][2] - h10, S[n0i][3] - h11);
                    pl[2] = pkbf(S[n1i][0] - h20, S[n1i][1] - h21);
                    pl[3] = pkbf(S[n1i][2] - h30, S[n1i][3] - h31);
                }
#pragma unroll
                for (int jn = 0; jn < 8; ++jn) {
                    const u32 a = swz(kt2 * 16 + a_lrow, jn);
                    u32 vb[2], vlb[2];
                    ldsm2t(vb[0], vb[1], stV + a);
                    ldsm2t(vlb[0], vlb[1], stVl + a);
                    mma16816(O[jn], ph, vb);
                    mma16816(O[jn], ph, vlb);
                    mma16816(O[jn], pl, vb);
                }
            }
        }

        __syncthreads();
        if (kt + 2 < NCH) load_chunk(kt + 2, s);
    }

    // ---- epilogue: normalize, split hi/lo, write g_ahi/g_alo [b,s,h*64+dd]
    const int b = bh >> 4, h = bh & 15;
    const float inv0 = 1.0f / lrow[0];
    const float inv1 = 1.0f / lrow[1];
    const int r0g = q0 + wm + (lane >> 2);
    const int colb = h * 64 + (lane & 3) * 2;
#pragma unroll
    for (int jn = 0; jn < 8; ++jn) {
        const int col = colb + jn * 8;
        {
            const float ox = O[jn][0] * inv0, oy = O[jn][1] * inv0;
            const bf16 hx = __float2bfloat16(ox), hy = __float2bfloat16(oy);
            const size_t idx = ((size_t)b * SQ + r0g) * DM + col;
            *(bf162*)(g_ahi + idx) = __halves2bfloat162(hx, hy);
            *(bf162*)(g_alo + idx) = __halves2bfloat162(
                __float2bfloat16(ox - __bfloat162float(hx)),
                __float2bfloat16(oy - __bfloat162float(hy)));
        }
        {
            const float ox = O[jn][2] * inv1, oy = O[jn][3] * inv1;
            const bf16 hx = __float2bfloat16(ox), hy = __float2bfloat16(oy);
            const size_t idx = ((size_t)b * SQ + r0g + 8) * DM + col;
            *(bf162*)(g_ahi + idx) = __halves2bfloat162(hx, hy);
            *(bf162*)(g_alo + idx) = __halves2bfloat162(
                __float2bfloat16(ox - __bfloat162float(hx)),
                __float2bfloat16(oy - __bfloat162float(hy)));
        }
    }
}

// ============================================================================
extern "C" void kernel_launch(void* const* d_in, const int* in_sizes, int n_in,
                              void* d_out, int out_size)
{
    const float* x    = (const float*)d_in[0];
    const float* attw = (const float*)d_in[1];
    const float* attb = (const float*)d_in[2];
    const float* pw   = (const float*)d_in[3];
    const float* pb   = (const float*)d_in[4];
    float* out = (float*)d_out;

    const int MMA_SMEM  = 2 * 65536;          // 131072
    const int ATTN_SMEM = 32768 + 2 * 32768;  // 98304
    cudaFuncSetAttribute(mma_gemm<0>,
        cudaFuncAttributeMaxDynamicSharedMemorySize, MMA_SMEM);
    cudaFuncSetAttribute(mma_gemm<1>,
        cudaFuncAttributeMaxDynamicSharedMemorySize, MMA_SMEM);
    cudaFuncSetAttribute(attn_mma,
        cudaFuncAttributeMaxDynamicSharedMemorySize, ATTN_SMEM);

    const int n4 = BS * DM / 4;

    conv_split_x<<<(n4 + 255) / 256, 256>>>(x, n4);
    conv_transpose<0><<<dim3(N3 / 32, DM / 32), 256>>>(attw, DM, N3);
    conv_transpose<1><<<dim3(DM / 32, DM / 32), 256>>>(pw, DM, DM);

    mma_gemm<0><<<dim3(N3 / 128, BS / 128), 256, MMA_SMEM>>>(attb, nullptr);

    attn_mma<<<dim3(SQ / 128, BB * NH), 256, ATTN_SMEM>>>();

    mma_gemm<1><<<dim3(DM / 128, BS / 128), 256, MMA_SMEM>>>(pb, out);
}

// round 7
// speedup vs baseline: 3.6120x; 1.0871x over previous
#include <cuda_runtime.h>
#include <cuda_bf16.h>
#include <cstdint>

#define BB   4
#define SQ   2048
#define DM   1024
#define NH   16
#define HD   64
#define BS   (BB*SQ)      // 8192
#define N3   (3*DM)       // 3072

typedef unsigned long long u64;
typedef unsigned int u32;
typedef __nv_bfloat16 bf16;
typedef __nv_bfloat162 bf162;

// Q pre-scale: 1/sqrt(64) * log2(e)  (softmax done in base-2 domain)
#define QSCALE 0.1803368801111204f

// ---------------- scratch (device globals; no allocation allowed) -----------
__device__ __align__(16) bf16 g_qhi[(size_t)BB*NH*SQ*HD];
__device__ __align__(16) bf16 g_qlo[(size_t)BB*NH*SQ*HD];
__device__ __align__(16) bf16 g_khi[(size_t)BB*NH*SQ*HD];
__device__ __align__(16) bf16 g_klo[(size_t)BB*NH*SQ*HD];
__device__ __align__(16) bf16 g_vhi[(size_t)BB*NH*SQ*HD];
__device__ __align__(16) bf16 g_vlo[(size_t)BB*NH*SQ*HD];

__device__ __align__(16) bf16 g_ahi[(size_t)BS*DM];
__device__ __align__(16) bf16 g_alo[(size_t)BS*DM];
__device__ __align__(16) bf16 g_bhi[(size_t)N3*DM];   // attw^T [3072][1024]
__device__ __align__(16) bf16 g_blo[(size_t)N3*DM];
__device__ __align__(16) bf16 g_phi[(size_t)DM*DM];   // pw^T [1024][1024]
__device__ __align__(16) bf16 g_plo[(size_t)DM*DM];

// ---------------- helpers -----------------------------------------------------
__device__ __forceinline__ void cp_async16(u32 smem, const void* g) {
    asm volatile("cp.async.cg.shared.global [%0], [%1], 16;" :: "r"(smem), "l"(g));
}
__device__ __forceinline__ void cp_commit()  { asm volatile("cp.async.commit_group;"); }
__device__ __forceinline__ void cp_wait0()   { asm volatile("cp.async.wait_group 0;"); }
__device__ __forceinline__ void cp_wait1()   { asm volatile("cp.async.wait_group 1;"); }
__device__ __forceinline__ u32 smem_u32(const void* p) {
    return (u32)__cvta_generic_to_shared(p);
}
__device__ __forceinline__ float ex2(float x) {
    float y; asm("ex2.approx.f32 %0, %1;" : "=f"(y) : "f"(x)); return y;
}
__device__ __forceinline__ void ldsm4(u32& r0, u32& r1, u32& r2, u32& r3, u32 a) {
    asm volatile("ldmatrix.sync.aligned.m8n8.x4.shared.b16 {%0,%1,%2,%3}, [%4];"
                 : "=r"(r0), "=r"(r1), "=r"(r2), "=r"(r3) : "r"(a));
}
__device__ __forceinline__ void ldsm4t(u32& r0, u32& r1, u32& r2, u32& r3, u32 a) {
    asm volatile("ldmatrix.sync.aligned.m8n8.x4.trans.shared.b16 {%0,%1,%2,%3}, [%4];"
                 : "=r"(r0), "=r"(r1), "=r"(r2), "=r"(r3) : "r"(a));
}
__device__ __forceinline__ void mma16816(float* d, const u32* a, const u32* b) {
    asm volatile(
        "mma.sync.aligned.m16n8k16.row.col.f32.bf16.bf16.f32 "
        "{%0,%1,%2,%3}, {%4,%5,%6,%7}, {%8,%9}, {%0,%1,%2,%3};"
        : "+f"(d[0]), "+f"(d[1]), "+f"(d[2]), "+f"(d[3])
        : "r"(a[0]), "r"(a[1]), "r"(a[2]), "r"(a[3]), "r"(b[0]), "r"(b[1]));
}
__device__ __forceinline__ u32 pkbf(float lo, float hi) {
    bf162 t = __halves2bfloat162(__float2bfloat16(lo), __float2bfloat16(hi));
    return *(u32*)&t;
}
// swizzled byte offset in a [rows x 128B] tile
__device__ __forceinline__ u32 swz(int r, int c) {
    return (u32)(r * 128 + ((c ^ (r & 7)) * 16));
}

// ============================================================================
// Conversion kernels
// ============================================================================
__global__ __launch_bounds__(256) void conv_split_x(const float* __restrict__ in, int n4)
{
    int i = blockIdx.x * 256 + threadIdx.x;
    if (i >= n4) return;
    float4 v = ((const float4*)in)[i];
    bf16 h0 = __float2bfloat16(v.x), h1 = __float2bfloat16(v.y);
    bf16 h2 = __float2bfloat16(v.z), h3 = __float2bfloat16(v.w);
    ((bf162*)g_ahi)[i*2]   = __halves2bfloat162(h0, h1);
    ((bf162*)g_ahi)[i*2+1] = __halves2bfloat162(h2, h3);
    ((bf162*)g_alo)[i*2]   = __halves2bfloat162(
        __float2bfloat16(v.x - __bfloat162float(h0)),
        __float2bfloat16(v.y - __bfloat162float(h1)));
    ((bf162*)g_alo)[i*2+1] = __halves2bfloat162(
        __float2bfloat16(v.z - __bfloat162float(h2)),
        __float2bfloat16(v.w - __bfloat162float(h3)));
}

template<int WSEL>    // 0 -> g_bhi/g_blo, 1 -> g_phi/g_plo
__global__ __launch_bounds__(256) void conv_transpose(const float* __restrict__ w,
                                                      int K, int N)
{
    bf16* hi = WSEL ? g_phi : g_bhi;
    bf16* lo = WSEL ? g_plo : g_blo;
    __shared__ float t[32][33];
    const int n0 = blockIdx.x * 32, k0 = blockIdx.y * 32;
    const int x = threadIdx.x & 31, y = (threadIdx.x >> 5) * 4;
#pragma unroll
    for (int r = 0; r < 4; ++r)
        t[y + r][x] = w[(size_t)(k0 + y + r) * N + n0 + x];
    __syncthreads();
#pragma unroll
    for (int r = 0; r < 4; ++r) {
        const int n = n0 + y + r, kk = k0 + x;
        const float f = t[x][y + r];
        bf16 h = __float2bfloat16(f);
        hi[(size_t)n * K + kk] = h;
        lo[(size_t)n * K + kk] = __float2bfloat16(f - __bfloat162float(h));
    }
}

// ============================================================================
// bf16x3 GEMM via mma.sync. 128x128 CTA, 8 warps (64x32), BK=64, 3 stages,
// ONE __syncthreads per chunk. MODE 0: qkv -> bf16 hi/lo scatter (Q scaled).
// MODE 1: proj -> fp32 out.
// Stage layout: 4 tiles [Ahi, Alo, Bhi, Blo] x 16KB = 64KB/stage, 3 stages.
// ============================================================================
template<int MODE>
__global__ __launch_bounds__(256) void mma_gemm(const float* __restrict__ bias,
                                                float* __restrict__ outp)
{
    extern __shared__ char smem[];
    const u32 sb = smem_u32(smem);
    const int tx = threadIdx.x, wid = tx >> 5, lane = tx & 31;
    const int m0 = blockIdx.y * 128, n0 = blockIdx.x * 128;
    const int K = DM;
    const int NCH = K / 64;

    const bf16* Ahi = g_ahi;
    const bf16* Alo = g_alo;
    const bf16* Bhi = MODE ? g_phi : g_bhi;
    const bf16* Blo = MODE ? g_plo : g_blo;

    const int wm = (wid & 1) * 64;
    const int wn = (wid >> 1) * 32;

    auto load_chunk = [&](int ci, int stage) {
        const int k0 = ci * 64;
#pragma unroll
        for (int t = 0; t < 4; ++t) {
            const bf16* src = (t == 0) ? Ahi : (t == 1) ? Alo
                            : (t == 2) ? Bhi : Blo;
            const int rbase = (t < 2) ? m0 : n0;
            const u32 tb = sb + (u32)(stage * 65536 + t * 16384);
#pragma unroll
            for (int u = 0; u < 4; ++u) {
                const int id = tx + 256 * u;
                const int r = id >> 3, c = id & 7;
                cp_async16(tb + swz(r, c),
                           src + (size_t)(rbase + r) * K + k0 + c * 8);
            }
        }
        cp_commit();
    };

    float acc[4][4][4];
#pragma unroll
    for (int mt = 0; mt < 4; ++mt)
#pragma unroll
        for (int nt = 0; nt < 4; ++nt)
#pragma unroll
            for (int e = 0; e < 4; ++e) acc[mt][nt][e] = 0.f;

    load_chunk(0, 0);
    load_chunk(1, 1);

    const int a_lrow = lane & 15;
    const int a_lc   = lane >> 4;
    const int b_lrow = lane & 7;
    const int b_lc   = (lane >> 3) & 1;
    const int b_sub  = (lane >> 4) & 1;

    for (int i = 0; i < NCH; ++i) {
        const int s = i % 3;
        if (i + 1 < NCH) cp_wait1(); else cp_wait0();
        __syncthreads();
        if (i + 2 < NCH) load_chunk(i + 2, (i + 2) % 3);

        const u32 tAhi = sb + (u32)(s * 65536);
        const u32 tAlo = tAhi + 16384;
        const u32 tBhi = tAhi + 32768;
        const u32 tBlo = tAhi + 49152;

#pragma unroll
        for (int ks = 0; ks < 4; ++ks) {
            u32 ah[4][4], al[4][4];
#pragma unroll
            for (int mt = 0; mt < 4; ++mt) {
                const int row = wm + mt * 16 + a_lrow;
                const int c   = ks * 2 + a_lc;
                ldsm4(ah[mt][0], ah[mt][1], ah[mt][2], ah[mt][3], tAhi + swz(row, c));
                ldsm4(al[mt][0], al[mt][1], al[mt][2], al[mt][3], tAlo + swz(row, c));
            }
            u32 bh[4][2], bl[4][2];
#pragma unroll
            for (int p = 0; p < 2; ++p) {
                const int row = wn + p * 16 + b_sub * 8 + b_lrow;
                const int c   = ks * 2 + b_lc;
                ldsm4(bh[2*p][0], bh[2*p][1], bh[2*p+1][0], bh[2*p+1][1],
                      tBhi + swz(row, c));
                ldsm4(bl[2*p][0], bl[2*p][1], bl[2*p+1][0], bl[2*p+1][1],
                      tBlo + swz(row, c));
            }
#pragma unroll
            for (int mt = 0; mt < 4; ++mt)
#pragma unroll
                for (int nt = 0; nt < 4; ++nt) {
                    mma16816(acc[mt][nt], ah[mt], bh[nt]);
                    mma16816(acc[mt][nt], ah[mt], bl[nt]);
                    mma16816(acc[mt][nt], al[mt], bh[nt]);
                }
        }
    }

    const int r_in  = lane >> 2;
    const int cpair = (lane & 3) * 2;

    if (MODE == 0) {
        const int seg = n0 >> 10;
        bf16 *dhi, *dlo;
        if (seg == 0)      { dhi = g_qhi; dlo = g_qlo; }
        else if (seg == 1) { dhi = g_khi; dlo = g_klo; }
        else               { dhi = g_vhi; dlo = g_vlo; }
        const float qs = (seg == 0) ? QSCALE : 1.0f;
#pragma unroll
        for (int mt = 0; mt < 4; ++mt)
#pragma unroll
            for (int nt = 0; nt < 4; ++nt)
#pragma unroll
                for (int hh = 0; hh < 2; ++hh) {
                    const int m = m0 + wm + mt * 16 + r_in + hh * 8;
                    const int n = n0 + wn + nt * 8 + cpair;
                    const int b  = m >> 11;
                    const int sI = m & 2047;
                    const int nn = n & 1023;
                    const int h  = nn >> 6, dd = nn & 63;
                    const float vx = (acc[mt][nt][hh*2+0] + bias[n]) * qs;
                    const float vy = (acc[mt][nt][hh*2+1] + bias[n+1]) * qs;
                    const bf16 hx = __float2bfloat16(vx);
                    const bf16 hy = __float2bfloat16(vy);
                    const size_t idx = ((((size_t)b * NH + h) * SQ + sI) << 6) + dd;
                    *(bf162*)(dhi + idx) = __halves2bfloat162(hx, hy);
                    *(bf162*)(dlo + idx) = __halves2bfloat162(
                        __float2bfloat16(vx - __bfloat162float(hx)),
                        __float2bfloat16(vy - __bfloat162float(hy)));
                }
    } else {
#pragma unroll
        for (int mt = 0; mt < 4; ++mt)
#pragma unroll
            for (int nt = 0; nt < 4; ++nt)
#pragma unroll
                for (int hh = 0; hh < 2; ++hh) {
                    const int m = m0 + wm + mt * 16 + r_in + hh * 8;
                    const int n = n0 + wn + nt * 8 + cpair;
                    float2 v;
                    v.x = acc[mt][nt][hh * 2 + 0] + bias[n];
                    v.y = acc[mt][nt][hh * 2 + 1] + bias[n + 1];
                    *(float2*)(outp + (size_t)m * DM + n) = v;
                }
    }
}

// ============================================================================
// Tensor-core flash attention. CTA = 128 q-rows x one (b,h). 8 warps, 16 rows
// each. K-chunks of 64 keys, 3 stages, ONE sync per chunk. bf16x3 split.
// smem: Qhi 16K | Qlo 16K | 3 stages x {Khi,Klo,Vhi,Vlo} 8K each = 128 KB.
// ============================================================================
__global__ __launch_bounds__(256) void attn_mma()
{
    extern __shared__ char smem[];
    const u32 sb = smem_u32(smem);
    const int tx = threadIdx.x, wid = tx >> 5, lane = tx & 31;
    const int qt = blockIdx.x, bh = blockIdx.y;
    const int q0 = qt * 128;
    const int wm = wid * 16;
    const size_t base = (size_t)bh * SQ * HD;

    const bf16* Qh = g_qhi + base;
    const bf16* Ql = g_qlo + base;
    const bf16* Kh = g_khi + base;
    const bf16* Kl = g_klo + base;
    const bf16* Vh = g_vhi + base;
    const bf16* Vl = g_vlo + base;

#pragma unroll
    for (int u = 0; u < 4; ++u) {
        const int id = tx + 256 * u;
        const int r = id >> 3, c = id & 7;
        cp_async16(sb + swz(r, c),         Qh + (size_t)(q0 + r) * HD + c * 8);
        cp_async16(sb + 16384 + swz(r, c), Ql + (size_t)(q0 + r) * HD + c * 8);
    }
    auto load_chunk = [&](int kt, int s) {
        const int k0 = kt * 64;
        const u32 st = sb + 32768 + (u32)s * 32768;
#pragma unroll
        for (int u = 0; u < 2; ++u) {
            const int id = tx + 256 * u;
            const int r = id >> 3, c = id & 7;
            cp_async16(st + swz(r, c),          Kh + (size_t)(k0 + r) * HD + c * 8);
            cp_async16(st + 8192 + swz(r, c),   Kl + (size_t)(k0 + r) * HD + c * 8);
            cp_async16(st + 16384 + swz(r, c),  Vh + (size_t)(k0 + r) * HD + c * 8);
            cp_async16(st + 24576 + swz(r, c),  Vl + (size_t)(k0 + r) * HD + c * 8);
        }
        cp_commit();
    };
    load_chunk(0, 0);                 // group includes Q loads
    const int NCH = 2 * qt + 2;
    if (NCH > 1) load_chunk(1, 1);

    u32 qh[4][4], ql[4][4];
    bool qloaded = false;

    float O[8][4];
#pragma unroll
    for (int jn = 0; jn < 8; ++jn)
#pragma unroll
        for (int e = 0; e < 4; ++e) O[jn][e] = 0.f;
    float mrow[2] = {-1e30f, -1e30f};
    float lrow[2] = {0.f, 0.f};

    const int a_lrow = lane & 15;
    const int a_lc   = lane >> 4;
    const int b_lrow = lane & 7;
    const int b_lc   = (lane >> 3) & 1;
    const int b_sub  = (lane >> 4) & 1;

    for (int kt = 0; kt < NCH; ++kt) {
        const int s = kt % 3;
        const int k0 = kt * 64;
        if (kt + 1 < NCH) cp_wait1(); else cp_wait0();
        __syncthreads();
        if (kt + 2 < NCH) load_chunk(kt + 2, (kt + 2) % 3);

        if (!qloaded) {
            qloaded = true;
#pragma unroll
            for (int kt2 = 0; kt2 < 4; ++kt2) {
                const u32 a = swz(wm + a_lrow, kt2 * 2 + a_lc);
                ldsm4(qh[kt2][0], qh[kt2][1], qh[kt2][2], qh[kt2][3], sb + a);
                ldsm4(ql[kt2][0], ql[kt2][1], ql[kt2][2], ql[kt2][3], sb + 16384 + a);
            }
        }

        const bool active = (k0 <= q0 + wm + 15);
        if (active) {
            const u32 stK  = sb + 32768 + (u32)s * 32768;
            const u32 stKl = stK + 8192;
            const u32 stV  = stK + 16384;
            const u32 stVl = stK + 24576;

            float S[8][4];
#pragma unroll
            for (int n = 0; n < 8; ++n)
#pragma unroll
                for (int e = 0; e < 4; ++e) S[n][e] = 0.f;

#pragma unroll
            for (int kt2 = 0; kt2 < 4; ++kt2) {
#pragma unroll
                for (int p = 0; p < 4; ++p) {
                    const int row = p * 16 + b_sub * 8 + b_lrow;
                    const u32 a = swz(row, kt2 * 2 + b_lc);
                    u32 k0b[2], k1b[2], k0l[2], k1l[2];
                    ldsm4(k0b[0], k0b[1], k1b[0], k1b[1], stK + a);
                    ldsm4(k0l[0], k0l[1], k1l[0], k1l[1], stKl + a);
                    mma16816(S[2*p],   qh[kt2], k0b);
                    mma16816(S[2*p],   qh[kt2], k0l);
                    mma16816(S[2*p],   ql[kt2], k0b);
                    mma16816(S[2*p+1], qh[kt2], k1b);
                    mma16816(S[2*p+1], qh[kt2], k1l);
                    mma16816(S[2*p+1], ql[kt2], k1b);
                }
            }

            if (k0 + 63 > q0 + wm) {
                const int r0g = q0 + wm + (lane >> 2);
                const int cb  = k0 + (lane & 3) * 2;
#pragma unroll
                for (int n = 0; n < 8; ++n)
#pragma unroll
                    for (int e = 0; e < 2; ++e) {
                        const int col = cb + n * 8 + e;
                        if (col > r0g)     S[n][e]     = -1e30f;
                        if (col > r0g + 8) S[n][2 + e] = -1e30f;
                    }
            }

            float m0n = mrow[0], m1n = mrow[1];
#pragma unroll
            for (int n = 0; n < 8; ++n) {
                m0n = fmaxf(m0n, fmaxf(S[n][0], S[n][1]));
                m1n = fmaxf(m1n, fmaxf(S[n][2], S[n][3]));
            }
            m0n = fmaxf(m0n, __shfl_xor_sync(0xffffffffu, m0n, 1));
            m0n = fmaxf(m0n, __shfl_xor_sync(0xffffffffu, m0n, 2));
            m1n = fmaxf(m1n, __shfl_xor_sync(0xffffffffu, m1n, 1));
            m1n = fmaxf(m1n, __shfl_xor_sync(0xffffffffu, m1n, 2));

            const float sc0 = ex2(mrow[0] - m0n);
            const float sc1 = ex2(mrow[1] - m1n);
            mrow[0] = m0n; mrow[1] = m1n;

            float ps0 = 0.f, ps1 = 0.f;
#pragma unroll
            for (int n = 0; n < 8; ++n) {
                S[n][0] = ex2(S[n][0] - m0n); ps0 += S[n][0];
                S[n][1] = ex2(S[n][1] - m0n); ps0 += S[n][1];
                S[n][2] = ex2(S[n][2] - m1n); ps1 += S[n][2];
                S[n][3] = ex2(S[n][3] - m1n); ps1 += S[n][3];
            }
            ps0 += __shfl_xor_sync(0xffffffffu, ps0, 1);
            ps0 += __shfl_xor_sync(0xffffffffu, ps0, 2);
            ps1 += __shfl_xor_sync(0xffffffffu, ps1, 1);
            ps1 += __shfl_xor_sync(0xffffffffu, ps1, 2);
            lrow[0] = lrow[0] * sc0 + ps0;
            lrow[1] = lrow[1] * sc1 + ps1;
#pragma unroll
            for (int jn = 0; jn < 8; ++jn) {
                O[jn][0] *= sc0; O[jn][1] *= sc0;
                O[jn][2] *= sc1; O[jn][3] *= sc1;
            }

#pragma unroll
            for (int kt2 = 0; kt2 < 4; ++kt2) {
                u32 ph[4], pl[4];
                {
                    const int n0i = 2 * kt2, n1i = 2 * kt2 + 1;
                    ph[0] = pkbf(S[n0i][0], S[n0i][1]);
                    ph[1] = pkbf(S[n0i][2], S[n0i][3]);
                    ph[2] = pkbf(S[n1i][0], S[n1i][1]);
                    ph[3] = pkbf(S[n1i][2], S[n1i][3]);
                    const float h00 = __bfloat162float(__float2bfloat16(S[n0i][0]));
                    const float h01 = __bfloat162float(__float2bfloat16(S[n0i][1]));
                    const float h10 = __bfloat162float(__float2bfloat16(S[n0i][2]));
                    const float h11 = __bfloat162float(__float2bfloat16(S[n0i][3]));
                    const float h20 = __bfloat162float(__float2bfloat16(S[n1i][0]));
                    const float h21 = __bfloat162float(__float2bfloat16(S[n1i][1]));
                    const float h30 = __bfloat162float(__float2bfloat16(S[n1i][2]));
                    const float h31 = __bfloat162float(__float2bfloat16(S[n1i][3]));
                    pl[0] = pkbf(S[n0i][0] - h00, S[n0i][1] - h01);
                    pl[1] = pkbf(S[n0i][2] - h10, S[n0i][3] - h11);
                    pl[2] = pkbf(S[n1i][0] - h20, S[n1i][1] - h21);
                    pl[3] = pkbf(S[n1i][2] - h30, S[n1i][3] - h31);
                }
#pragma unroll
                for (int jp = 0; jp < 4; ++jp) {
                    const u32 a = swz(kt2 * 16 + a_lrow, jp * 2 + ((lane >> 4) & 1));
                    u32 v0[2], v1[2], vl0[2], vl1[2];
                    ldsm4t(v0[0], v0[1], v1[0], v1[1], stV + a);
                    ldsm4t(vl0[0], vl0[1], vl1[0], vl1[1], stVl + a);
                    mma16816(O[2*jp],   ph, v0);
                    mma16816(O[2*jp],   ph, vl0);
                    mma16816(O[2*jp],   pl, v0);
                    mma16816(O[2*jp+1], ph, v1);
                    mma16816(O[2*jp+1], ph, vl1);
                    mma16816(O[2*jp+1], pl, v1);
                }
            }
        }
    }

    // ---- epilogue: normalize, split hi/lo, write g_ahi/g_alo [b,s,h*64+dd]
    const int b = bh >> 4, h = bh & 15;
    const float inv0 = 1.0f / lrow[0];
    const float inv1 = 1.0f / lrow[1];
    const int r0g = q0 + wm + (lane >> 2);
    const int colb = h * 64 + (lane & 3) * 2;
#pragma unroll
    for (int jn = 0; jn < 8; ++jn) {
        const int col = colb + jn * 8;
        {
            const float ox = O[jn][0] * inv0, oy = O[jn][1] * inv0;
            const bf16 hx = __float2bfloat16(ox), hy = __float2bfloat16(oy);
            const size_t idx = ((size_t)b * SQ + r0g) * DM + col;
            *(bf162*)(g_ahi + idx) = __halves2bfloat162(hx, hy);
            *(bf162*)(g_alo + idx) = __halves2bfloat162(
                __float2bfloat16(ox - __bfloat162float(hx)),
                __float2bfloat16(oy - __bfloat162float(hy)));
        }
        {
            const float ox = O[jn][2] * inv1, oy = O[jn][3] * inv1;
            const bf16 hx = __float2bfloat16(ox), hy = __float2bfloat16(oy);
            const size_t idx = ((size_t)b * SQ + r0g + 8) * DM + col;
            *(bf162*)(g_ahi + idx) = __halves2bfloat162(hx, hy);
            *(bf162*)(g_alo + idx) = __halves2bfloat162(
                __float2bfloat16(ox - __bfloat162float(hx)),
                __float2bfloat16(oy - __bfloat162float(hy)));
        }
    }
}

// ============================================================================
extern "C" void kernel_launch(void* const* d_in, const int* in_sizes, int n_in,
                              void* d_out, int out_size)
{
    const float* x    = (const float*)d_in[0];
    const float* attw = (const float*)d_in[1];
    const float* attb = (const float*)d_in[2];
    const float* pw   = (const float*)d_in[3];
    const float* pb   = (const float*)d_in[4];
    float* out = (float*)d_out;

    const int MMA_SMEM  = 3 * 65536;          // 196608
    const int ATTN_SMEM = 32768 + 3 * 32768;  // 131072
    cudaFuncSetAttribute(mma_gemm<0>,
        cudaFuncAttributeMaxDynamicSharedMemorySize, MMA_SMEM);
    cudaFuncSetAttribute(mma_gemm<1>,
        cudaFuncAttributeMaxDynamicSharedMemorySize, MMA_SMEM);
    cudaFuncSetAttribute(attn_mma,
        cudaFuncAttributeMaxDynamicSharedMemorySize, ATTN_SMEM);

    const int n4 = BS * DM / 4;

    conv_split_x<<<(n4 + 255) / 256, 256>>>(x, n4);
    conv_transpose<0><<<dim3(N3 / 32, DM / 32), 256>>>(attw, DM, N3);
    conv_transpose<1><<<dim3(DM / 32, DM / 32), 256>>>(pw, DM, DM);

    mma_gemm<0><<<dim3(N3 / 128, BS / 128), 256, MMA_SMEM>>>(attb, nullptr);

    attn_mma<<<dim3(SQ / 128, BB * NH), 256, ATTN_SMEM>>>();

    mma_gemm<1><<<dim3(DM / 128, BS / 128), 256, MMA_SMEM>>>(pb, out);
}

// round 8
// speedup vs baseline: 3.6206x; 1.0024x over previous
#include <cuda_runtime.h>
#include <cuda_bf16.h>
#include <cstdint>

#define BB   4
#define SQ   2048
#define DM   1024
#define NH   16
#define HD   64
#define BS   (BB*SQ)      // 8192
#define N3   (3*DM)       // 3072

typedef unsigned long long u64;
typedef unsigned int u32;
typedef __nv_bfloat16 bf16;
typedef __nv_bfloat162 bf162;

// Q pre-scale: 1/sqrt(64) * log2(e)  (softmax done in base-2 domain)
#define QSCALE 0.1803368801111204f

// ---------------- scratch (device globals; no allocation allowed) -----------
__device__ __align__(16) bf16 g_qhi[(size_t)BB*NH*SQ*HD];
__device__ __align__(16) bf16 g_qlo[(size_t)BB*NH*SQ*HD];
__device__ __align__(16) bf16 g_khi[(size_t)BB*NH*SQ*HD];
__device__ __align__(16) bf16 g_klo[(size_t)BB*NH*SQ*HD];
__device__ __align__(16) bf16 g_vhi[(size_t)BB*NH*SQ*HD];
__device__ __align__(16) bf16 g_vlo[(size_t)BB*NH*SQ*HD];

__device__ __align__(16) bf16 g_ahi[(size_t)BS*DM];
__device__ __align__(16) bf16 g_alo[(size_t)BS*DM];
__device__ __align__(16) bf16 g_bhi[(size_t)N3*DM];   // attw^T [3072][1024]
__device__ __align__(16) bf16 g_blo[(size_t)N3*DM];
__device__ __align__(16) bf16 g_phi[(size_t)DM*DM];   // pw^T [1024][1024]
__device__ __align__(16) bf16 g_plo[(size_t)DM*DM];

// ---------------- helpers -----------------------------------------------------
__device__ __forceinline__ void cp_async16(u32 smem, const void* g) {
    asm volatile("cp.async.cg.shared.global [%0], [%1], 16;" :: "r"(smem), "l"(g));
}
__device__ __forceinline__ void cp_commit()  { asm volatile("cp.async.commit_group;"); }
__device__ __forceinline__ void cp_wait0()   { asm volatile("cp.async.wait_group 0;"); }
__device__ __forceinline__ void cp_wait1()   { asm volatile("cp.async.wait_group 1;"); }
__device__ __forceinline__ u32 smem_u32(const void* p) {
    return (u32)__cvta_generic_to_shared(p);
}
__device__ __forceinline__ float ex2(float x) {
    float y; asm("ex2.approx.f32 %0, %1;" : "=f"(y) : "f"(x)); return y;
}
__device__ __forceinline__ void ldsm4(u32& r0, u32& r1, u32& r2, u32& r3, u32 a) {
    asm volatile("ldmatrix.sync.aligned.m8n8.x4.shared.b16 {%0,%1,%2,%3}, [%4];"
                 : "=r"(r0), "=r"(r1), "=r"(r2), "=r"(r3) : "r"(a));
}
__device__ __forceinline__ void ldsm4t(u32& r0, u32& r1, u32& r2, u32& r3, u32 a) {
    asm volatile("ldmatrix.sync.aligned.m8n8.x4.trans.shared.b16 {%0,%1,%2,%3}, [%4];"
                 : "=r"(r0), "=r"(r1), "=r"(r2), "=r"(r3) : "r"(a));
}
__device__ __forceinline__ void mma16816(float* d, const u32* a, const u32* b) {
    asm volatile(
        "mma.sync.aligned.m16n8k16.row.col.f32.bf16.bf16.f32 "
        "{%0,%1,%2,%3}, {%4,%5,%6,%7}, {%8,%9}, {%0,%1,%2,%3};"
        : "+f"(d[0]), "+f"(d[1]), "+f"(d[2]), "+f"(d[3])
        : "r"(a[0]), "r"(a[1]), "r"(a[2]), "r"(a[3]), "r"(b[0]), "r"(b[1]));
}
__device__ __forceinline__ u32 pkbf(float lo, float hi) {
    bf162 t = __halves2bfloat162(__float2bfloat16(lo), __float2bfloat16(hi));
    return *(u32*)&t;
}
// swizzled byte offset in a [rows x 128B] tile (SW128 style)
__device__ __forceinline__ u32 swz(int r, int c) {
    return (u32)(r * 128 + ((c ^ (r & 7)) * 16));
}
// swizzled byte offset in a [rows x 64B] tile (SW64 style): 4 chunks/row
__device__ __forceinline__ u32 swz64(int r, int c) {
    return (u32)(r * 64 + ((c ^ ((r >> 1) & 3)) * 16));
}

// ============================================================================
// Conversion kernels
// ============================================================================
__global__ __launch_bounds__(256) void conv_split_x(const float* __restrict__ in, int n4)
{
    int i = blockIdx.x * 256 + threadIdx.x;
    if (i >= n4) return;
    float4 v = ((const float4*)in)[i];
    bf16 h0 = __float2bfloat16(v.x), h1 = __float2bfloat16(v.y);
    bf16 h2 = __float2bfloat16(v.z), h3 = __float2bfloat16(v.w);
    ((bf162*)g_ahi)[i*2]   = __halves2bfloat162(h0, h1);
    ((bf162*)g_ahi)[i*2+1] = __halves2bfloat162(h2, h3);
    ((bf162*)g_alo)[i*2]   = __halves2bfloat162(
        __float2bfloat16(v.x - __bfloat162float(h0)),
        __float2bfloat16(v.y - __bfloat162float(h1)));
    ((bf162*)g_alo)[i*2+1] = __halves2bfloat162(
        __float2bfloat16(v.z - __bfloat162float(h2)),
        __float2bfloat16(v.w - __bfloat162float(h3)));
}

template<int WSEL>    // 0 -> g_bhi/g_blo, 1 -> g_phi/g_plo
__global__ __launch_bounds__(256) void conv_transpose(const float* __restrict__ w,
                                                      int K, int N)
{
    bf16* hi = WSEL ? g_phi : g_bhi;
    bf16* lo = WSEL ? g_plo : g_blo;
    __shared__ float t[32][33];
    const int n0 = blockIdx.x * 32, k0 = blockIdx.y * 32;
    const int x = threadIdx.x & 31, y = (threadIdx.x >> 5) * 4;
#pragma unroll
    for (int r = 0; r < 4; ++r)
        t[y + r][x] = w[(size_t)(k0 + y + r) * N + n0 + x];
    __syncthreads();
#pragma unroll
    for (int r = 0; r < 4; ++r) {
        const int n = n0 + y + r, kk = k0 + x;
        const float f = t[x][y + r];
        bf16 h = __float2bfloat16(f);
        hi[(size_t)n * K + kk] = h;
        lo[(size_t)n * K + kk] = __float2bfloat16(f - __bfloat162float(h));
    }
}

// ============================================================================
// bf16x3 GEMM via mma.sync. 128x128 CTA, 8 warps (64x32), BK=32, 3 stages,
// one sync per chunk, 96KB smem -> 2 CTAs/SM.
// Stage layout: 4 tiles [Ahi, Alo, Bhi, Blo] x 8KB (128 rows x 64B, SW64).
// ============================================================================
template<int MODE>
__global__ __launch_bounds__(256, 2) void mma_gemm(const float* __restrict__ bias,
                                                   float* __restrict__ outp)
{
    extern __shared__ char smem[];
    const u32 sb = smem_u32(smem);
    const int tx = threadIdx.x, wid = tx >> 5, lane = tx & 31;
    const int m0 = blockIdx.y * 128, n0 = blockIdx.x * 128;
    const int K = DM;
    const int NCH = K / 32;                 // 32 chunks

    const bf16* Ahi = g_ahi;
    const bf16* Alo = g_alo;
    const bf16* Bhi = MODE ? g_phi : g_bhi;
    const bf16* Blo = MODE ? g_plo : g_blo;

    const int wm = (wid & 1) * 64;
    const int wn = (wid >> 1) * 32;

    auto load_chunk = [&](int ci, int stage) {
        const int k0 = ci * 32;
#pragma unroll
        for (int t = 0; t < 4; ++t) {
            const bf16* src = (t == 0) ? Ahi : (t == 1) ? Alo
                            : (t == 2) ? Bhi : Blo;
            const int rbase = (t < 2) ? m0 : n0;
            const u32 tb = sb + (u32)(stage * 32768 + t * 8192);
#pragma unroll
            for (int u = 0; u < 2; ++u) {
                const int id = tx + 256 * u;
                const int r = id >> 2, c = id & 3;
                cp_async16(tb + swz64(r, c),
                           src + (size_t)(rbase + r) * K + k0 + c * 8);
            }
        }
        cp_commit();
    };

    float acc[4][4][4];
#pragma unroll
    for (int mt = 0; mt < 4; ++mt)
#pragma unroll
        for (int nt = 0; nt < 4; ++nt)
#pragma unroll
            for (int e = 0; e < 4; ++e) acc[mt][nt][e] = 0.f;

    load_chunk(0, 0);
    load_chunk(1, 1);

    const int a_lrow = lane & 15;
    const int a_lc   = lane >> 4;
    const int b_lrow = lane & 7;
    const int b_lc   = (lane >> 3) & 1;
    const int b_sub  = (lane >> 4) & 1;

    for (int i = 0; i < NCH; ++i) {
        const int s = i % 3;
        if (i + 1 < NCH) cp_wait1(); else cp_wait0();
        __syncthreads();
        if (i + 2 < NCH) load_chunk(i + 2, (i + 2) % 3);

        const u32 tAhi = sb + (u32)(s * 32768);
        const u32 tAlo = tAhi + 8192;
        const u32 tBhi = tAhi + 16384;
        const u32 tBlo = tAhi + 24576;

#pragma unroll
        for (int ks = 0; ks < 2; ++ks) {
            u32 ah[4][4], al[4][4];
#pragma unroll
            for (int mt = 0; mt < 4; ++mt) {
                const int row = wm + mt * 16 + a_lrow;
                const int c   = ks * 2 + a_lc;
                ldsm4(ah[mt][0], ah[mt][1], ah[mt][2], ah[mt][3], tAhi + swz64(row, c));
                ldsm4(al[mt][0], al[mt][1], al[mt][2], al[mt][3], tAlo + swz64(row, c));
            }
            u32 bh[4][2], bl[4][2];
#pragma unroll
            for (int p = 0; p < 2; ++p) {
                const int row = wn + p * 16 + b_sub * 8 + b_lrow;
                const int c   = ks * 2 + b_lc;
                ldsm4(bh[2*p][0], bh[2*p][1], bh[2*p+1][0], bh[2*p+1][1],
                      tBhi + swz64(row, c));
                ldsm4(bl[2*p][0], bl[2*p][1], bl[2*p+1][0], bl[2*p+1][1],
                      tBlo + swz64(row, c));
            }
#pragma unroll
            for (int mt = 0; mt < 4; ++mt)
#pragma unroll
                for (int nt = 0; nt < 4; ++nt) {
                    mma16816(acc[mt][nt], ah[mt], bh[nt]);
                    mma16816(acc[mt][nt], ah[mt], bl[nt]);
                    mma16816(acc[mt][nt], al[mt], bh[nt]);
                }
        }
    }

    const int r_in  = lane >> 2;
    const int cpair = (lane & 3) * 2;

    if (MODE == 0) {
        const int seg = n0 >> 10;
        bf16 *dhi, *dlo;
        if (seg == 0)      { dhi = g_qhi; dlo = g_qlo; }
        else if (seg == 1) { dhi = g_khi; dlo = g_klo; }
        else               { dhi = g_vhi; dlo = g_vlo; }
        const float qs = (seg == 0) ? QSCALE : 1.0f;
#pragma unroll
        for (int mt = 0; mt < 4; ++mt)
#pragma unroll
            for (int nt = 0; nt < 4; ++nt)
#pragma unroll
                for (int hh = 0; hh < 2; ++hh) {
                    const int m = m0 + wm + mt * 16 + r_in + hh * 8;
                    const int n = n0 + wn + nt * 8 + cpair;
                    const int b  = m >> 11;
                    const int sI = m & 2047;
                    const int nn = n & 1023;
                    const int h  = nn >> 6, dd = nn & 63;
                    const float vx = (acc[mt][nt][hh*2+0] + bias[n]) * qs;
                    const float vy = (acc[mt][nt][hh*2+1] + bias[n+1]) * qs;
                    const bf16 hx = __float2bfloat16(vx);
                    const bf16 hy = __float2bfloat16(vy);
                    const size_t idx = ((((size_t)b * NH + h) * SQ + sI) << 6) + dd;
                    *(bf162*)(dhi + idx) = __halves2bfloat162(hx, hy);
                    *(bf162*)(dlo + idx) = __halves2bfloat162(
                        __float2bfloat16(vx - __bfloat162float(hx)),
                        __float2bfloat16(vy - __bfloat162float(hy)));
                }
    } else {
#pragma unroll
        for (int mt = 0; mt < 4; ++mt)
#pragma unroll
            for (int nt = 0; nt < 4; ++nt)
#pragma unroll
                for (int hh = 0; hh < 2; ++hh) {
                    const int m = m0 + wm + mt * 16 + r_in + hh * 8;
                    const int n = n0 + wn + nt * 8 + cpair;
                    float2 v;
                    v.x = acc[mt][nt][hh * 2 + 0] + bias[n];
                    v.y = acc[mt][nt][hh * 2 + 1] + bias[n + 1];
                    *(float2*)(outp + (size_t)m * DM + n) = v;
                }
    }
}

// ============================================================================
// Tensor-core flash attention. CTA = 128 q-rows x one (b,h). 8 warps, 16 rows
// each. K-chunks of 64 keys, 2 stages (2 syncs/chunk), 96KB smem ->
// 2 CTAs/SM. Q frags reloaded from smem each chunk (register budget).
// smem: Qhi 16K | Qlo 16K | 2 stages x {Khi,Klo,Vhi,Vlo} 8K each = 96 KB.
// ============================================================================
__global__ __launch_bounds__(256, 2) void attn_mma()
{
    extern __shared__ char smem[];
    const u32 sb = smem_u32(smem);
    const int tx = threadIdx.x, wid = tx >> 5, lane = tx & 31;
    const int qt = blockIdx.x, bh = blockIdx.y;
    const int q0 = qt * 128;
    const int wm = wid * 16;
    const size_t base = (size_t)bh * SQ * HD;

    const bf16* Qh = g_qhi + base;
    const bf16* Ql = g_qlo + base;
    const bf16* Kh = g_khi + base;
    const bf16* Kl = g_klo + base;
    const bf16* Vh = g_vhi + base;
    const bf16* Vl = g_vlo + base;

#pragma unroll
    for (int u = 0; u < 4; ++u) {
        const int id = tx + 256 * u;
        const int r = id >> 3, c = id & 7;
        cp_async16(sb + swz(r, c),         Qh + (size_t)(q0 + r) * HD + c * 8);
        cp_async16(sb + 16384 + swz(r, c), Ql + (size_t)(q0 + r) * HD + c * 8);
    }
    auto load_chunk = [&](int kt, int s) {
        const int k0 = kt * 64;
        const u32 st = sb + 32768 + (u32)s * 32768;
#pragma unroll
        for (int u = 0; u < 2; ++u) {
            const int id = tx + 256 * u;
            const int r = id >> 3, c = id & 7;
            cp_async16(st + swz(r, c),          Kh + (size_t)(k0 + r) * HD + c * 8);
            cp_async16(st + 8192 + swz(r, c),   Kl + (size_t)(k0 + r) * HD + c * 8);
            cp_async16(st + 16384 + swz(r, c),  Vh + (size_t)(k0 + r) * HD + c * 8);
            cp_async16(st + 24576 + swz(r, c),  Vl + (size_t)(k0 + r) * HD + c * 8);
        }
        cp_commit();
    };
    load_chunk(0, 0);                 // group includes Q loads
    const int NCH = 2 * qt + 2;
    if (NCH > 1) load_chunk(1, 1);

    float O[8][4];
#pragma unroll
    for (int jn = 0; jn < 8; ++jn)
#pragma unroll
        for (int e = 0; e < 4; ++e) O[jn][e] = 0.f;
    float mrow[2] = {-1e30f, -1e30f};
    float lrow[2] = {0.f, 0.f};

    const int a_lrow = lane & 15;
    const int a_lc   = lane >> 4;
    const int b_lrow = lane & 7;
    const int b_lc   = (lane >> 3) & 1;
    const int b_sub  = (lane >> 4) & 1;

    for (int kt = 0; kt < NCH; ++kt) {
        const int s = kt & 1;
        const int k0 = kt * 64;
        if (kt + 1 < NCH) cp_wait1(); else cp_wait0();
        __syncthreads();

        const bool active = (k0 <= q0 + wm + 15);
        if (active) {
            const u32 stK  = sb + 32768 + (u32)s * 32768;
            const u32 stKl = stK + 8192;
            const u32 stV  = stK + 16384;
            const u32 stVl = stK + 24576;

            float S[8][4];
#pragma unroll
            for (int n = 0; n < 8; ++n)
#pragma unroll
                for (int e = 0; e < 4; ++e) S[n][e] = 0.f;

#pragma unroll
            for (int kt2 = 0; kt2 < 4; ++kt2) {
                u32 qh[4], ql[4];
                {
                    const u32 a = swz(wm + a_lrow, kt2 * 2 + a_lc);
                    ldsm4(qh[0], qh[1], qh[2], qh[3], sb + a);
                    ldsm4(ql[0], ql[1], ql[2], ql[3], sb + 16384 + a);
                }
#pragma unroll
                for (int p = 0; p < 4; ++p) {
                    const int row = p * 16 + b_sub * 8 + b_lrow;
                    const u32 a = swz(row, kt2 * 2 + b_lc);
                    u32 k0b[2], k1b[2], k0l[2], k1l[2];
                    ldsm4(k0b[0], k0b[1], k1b[0], k1b[1], stK + a);
                    ldsm4(k0l[0], k0l[1], k1l[0], k1l[1], stKl + a);
                    mma16816(S[2*p],   qh, k0b);
                    mma16816(S[2*p],   qh, k0l);
                    mma16816(S[2*p],   ql, k0b);
                    mma16816(S[2*p+1], qh, k1b);
                    mma16816(S[2*p+1], qh, k1l);
                    mma16816(S[2*p+1], ql, k1b);
                }
            }

            if (k0 + 63 > q0 + wm) {
                const int r0g = q0 + wm + (lane >> 2);
                const int cb  = k0 + (lane & 3) * 2;
#pragma unroll
                for (int n = 0; n < 8; ++n)
#pragma unroll
                    for (int e = 0; e < 2; ++e) {
                        const int col = cb + n * 8 + e;
                        if (col > r0g)     S[n][e]     = -1e30f;
                        if (col > r0g + 8) S[n][2 + e] = -1e30f;
                    }
            }

            float m0n = mrow[0], m1n = mrow[1];
#pragma unroll
            for (int n = 0; n < 8; ++n) {
                m0n = fmaxf(m0n, fmaxf(S[n][0], S[n][1]));
                m1n = fmaxf(m1n, fmaxf(S[n][2], S[n][3]));
            }
            m0n = fmaxf(m0n, __shfl_xor_sync(0xffffffffu, m0n, 1));
            m0n = fmaxf(m0n, __shfl_xor_sync(0xffffffffu, m0n, 2));
            m1n = fmaxf(m1n, __shfl_xor_sync(0xffffffffu, m1n, 1));
            m1n = fmaxf(m1n, __shfl_xor_sync(0xffffffffu, m1n, 2));

            const float sc0 = ex2(mrow[0] - m0n);
            const float sc1 = ex2(mrow[1] - m1n);
            mrow[0] = m0n; mrow[1] = m1n;

            float ps0 = 0.f, ps1 = 0.f;
#pragma unroll
            for (int n = 0; n < 8; ++n) {
                S[n][0] = ex2(S[n][0] - m0n); ps0 += S[n][0];
                S[n][1] = ex2(S[n][1] - m0n); ps0 += S[n][1];
                S[n][2] = ex2(S[n][2] - m1n); ps1 += S[n][2];
                S[n][3] = ex2(S[n][3] - m1n); ps1 += S[n][3];
            }
            ps0 += __shfl_xor_sync(0xffffffffu, ps0, 1);
            ps0 += __shfl_xor_sync(0xffffffffu, ps0, 2);
            ps1 += __shfl_xor_sync(0xffffffffu, ps1, 1);
            ps1 += __shfl_xor_sync(0xffffffffu, ps1, 2);
            lrow[0] = lrow[0] * sc0 + ps0;
            lrow[1] = lrow[1] * sc1 + ps1;
#pragma unroll
            for (int jn = 0; jn < 8; ++jn) {
                O[jn][0] *= sc0; O[jn][1] *= sc0;
                O[jn][2] *= sc1; O[jn][3] *= sc1;
            }

#pragma unroll
            for (int kt2 = 0; kt2 < 4; ++kt2) {
                u32 ph[4], pl[4];
                {
                    const int n0i = 2 * kt2, n1i = 2 * kt2 + 1;
                    ph[0] = pkbf(S[n0i][0], S[n0i][1]);
                    ph[1] = pkbf(S[n0i][2], S[n0i][3]);
                    ph[2] = pkbf(S[n1i][0], S[n1i][1]);
                    ph[3] = pkbf(S[n1i][2], S[n1i][3]);
                    const float h00 = __bfloat162float(__float2bfloat16(S[n0i][0]));
                    const float h01 = __bfloat162float(__float2bfloat16(S[n0i][1]));
                    const float h10 = __bfloat162float(__float2bfloat16(S[n0i][2]));
                    const float h11 = __bfloat162float(__float2bfloat16(S[n0i][3]));
                    const float h20 = __bfloat162float(__float2bfloat16(S[n1i][0]));
                    const float h21 = __bfloat162float(__float2bfloat16(S[n1i][1]));
                    const float h30 = __bfloat162float(__float2bfloat16(S[n1i][2]));
                    const float h31 = __bfloat162float(__float2bfloat16(S[n1i][3]));
                    pl[0] = pkbf(S[n0i][0] - h00, S[n0i][1] - h01);
                    pl[1] = pkbf(S[n0i][2] - h10, S[n0i][3] - h11);
                    pl[2] = pkbf(S[n1i][0] - h20, S[n1i][1] - h21);
                    pl[3] = pkbf(S[n1i][2] - h30, S[n1i][3] - h31);
                }
#pragma unroll
                for (int jp = 0; jp < 4; ++jp) {
                    const u32 a = swz(kt2 * 16 + a_lrow, jp * 2 + ((lane >> 4) & 1));
                    u32 v0[2], v1[2], vl0[2], vl1[2];
                    ldsm4t(v0[0], v0[1], v1[0], v1[1], stV + a);
                    ldsm4t(vl0[0], vl0[1], vl1[0], vl1[1], stVl + a);
                    mma16816(O[2*jp],   ph, v0);
                    mma16816(O[2*jp],   ph, vl0);
                    mma16816(O[2*jp],   pl, v0);
                    mma16816(O[2*jp+1], ph, v1);
                    mma16816(O[2*jp+1], ph, vl1);
                    mma16816(O[2*jp+1], pl, v1);
                }
            }
        }

        __syncthreads();
        if (kt + 2 < NCH) load_chunk(kt + 2, s);
    }

    // ---- epilogue: normalize, split hi/lo, write g_ahi/g_alo [b,s,h*64+dd]
    const int b = bh >> 4, h = bh & 15;
    const float inv0 = 1.0f / lrow[0];
    const float inv1 = 1.0f / lrow[1];
    const int r0g = q0 + wm + (lane >> 2);
    const int colb = h * 64 + (lane & 3) * 2;
#pragma unroll
    for (int jn = 0; jn < 8; ++jn) {
        const int col = colb + jn * 8;
        {
            const float ox = O[jn][0] * inv0, oy = O[jn][1] * inv0;
            const bf16 hx = __float2bfloat16(ox), hy = __float2bfloat16(oy);
            const size_t idx = ((size_t)b * SQ + r0g) * DM + col;
            *(bf162*)(g_ahi + idx) = __halves2bfloat162(hx, hy);
            *(bf162*)(g_alo + idx) = __halves2bfloat162(
                __float2bfloat16(ox - __bfloat162float(hx)),
                __float2bfloat16(oy - __bfloat162float(hy)));
        }
        {
            const float ox = O[jn][2] * inv1, oy = O[jn][3] * inv1;
            const bf16 hx = __float2bfloat16(ox), hy = __float2bfloat16(oy);
            const size_t idx = ((size_t)b * SQ + r0g + 8) * DM + col;
            *(bf162*)(g_ahi + idx) = __halves2bfloat162(hx, hy);
            *(bf162*)(g_alo + idx) = __halves2bfloat162(
                __float2bfloat16(ox - __bfloat162float(hx)),
                __float2bfloat16(oy - __bfloat162float(hy)));
        }
    }
}

// ============================================================================
extern "C" void kernel_launch(void* const* d_in, const int* in_sizes, int n_in,
                              void* d_out, int out_size)
{
    const float* x    = (const float*)d_in[0];
    const float* attw = (const float*)d_in[1];
    const float* attb = (const float*)d_in[2];
    const float* pw   = (const float*)d_in[3];
    const float* pb   = (const float*)d_in[4];
    float* out = (float*)d_out;

    const int MMA_SMEM  = 3 * 32768;          // 98304 -> 2 CTAs/SM
    const int ATTN_SMEM = 32768 + 2 * 32768;  // 98304 -> 2 CTAs/SM
    cudaFuncSetAttribute(mma_gemm<0>,
        cudaFuncAttributeMaxDynamicSharedMemorySize, MMA_SMEM);
    cudaFuncSetAttribute(mma_gemm<1>,
        cudaFuncAttributeMaxDynamicSharedMemorySize, MMA_SMEM);
    cudaFuncSetAttribute(attn_mma,
        cudaFuncAttributeMaxDynamicSharedMemorySize, ATTN_SMEM);

    const int n4 = BS * DM / 4;

    conv_split_x<<<(n4 + 255) / 256, 256>>>(x, n4);
    conv_transpose<0><<<dim3(N3 / 32, DM / 32), 256>>>(attw, DM, N3);
    conv_transpose<1><<<dim3(DM / 32, DM / 32), 256>>>(pw, DM, DM);

    mma_gemm<0><<<dim3(N3 / 128, BS / 128), 256, MMA_SMEM>>>(attb, nullptr);

    attn_mma<<<dim3(SQ / 128, BB * NH), 256, ATTN_SMEM>>>();

    mma_gemm<1><<<dim3(DM / 128, BS / 128), 256, MMA_SMEM>>>(pb, out);
}

// round 9
// speedup vs baseline: 4.3914x; 1.2129x over previous
#include <cuda_runtime.h>
#include <cuda_bf16.h>
#include <cstdint>

#define BB   4
#define SQ   2048
#define DM   1024
#define NH   16
#define HD   64
#define BS   (BB*SQ)      // 8192
#define N3   (3*DM)       // 3072

typedef unsigned long long u64;
typedef unsigned int u32;
typedef __nv_bfloat16 bf16;
typedef __nv_bfloat162 bf162;

// Q pre-scale: 1/sqrt(64) * log2(e)  (softmax done in base-2 domain)
#define QSCALE 0.1803368801111204f

// ---------------- scratch (device globals; no allocation allowed) -----------
__device__ __align__(16) bf16 g_qhi[(size_t)BB*NH*SQ*HD];
__device__ __align__(16) bf16 g_qlo[(size_t)BB*NH*SQ*HD];
__device__ __align__(16) bf16 g_khi[(size_t)BB*NH*SQ*HD];
__device__ __align__(16) bf16 g_klo[(size_t)BB*NH*SQ*HD];
__device__ __align__(16) bf16 g_vhi[(size_t)BB*NH*SQ*HD];
__device__ __align__(16) bf16 g_vlo[(size_t)BB*NH*SQ*HD];

__device__ __align__(16) float g_xtf[(size_t)BS*DM];   // x, tf32-rounded
__device__ __align__(16) float g_atf[(size_t)BS*DM];   // attn out, tf32-rounded
__device__ __align__(16) float g_wq[(size_t)N3*DM];    // attw^T [3072][1024] tf32
__device__ __align__(16) float g_wp[(size_t)DM*DM];    // pw^T  [1024][1024] tf32

// ---------------- helpers -----------------------------------------------------
__device__ __forceinline__ void cp_async16(u32 smem, const void* g) {
    asm volatile("cp.async.cg.shared.global [%0], [%1], 16;" :: "r"(smem), "l"(g));
}
__device__ __forceinline__ void cp_commit()  { asm volatile("cp.async.commit_group;"); }
__device__ __forceinline__ void cp_wait0()   { asm volatile("cp.async.wait_group 0;"); }
__device__ __forceinline__ void cp_wait1()   { asm volatile("cp.async.wait_group 1;"); }
__device__ __forceinline__ u32 smem_u32(const void* p) {
    return (u32)__cvta_generic_to_shared(p);
}
__device__ __forceinline__ float ex2(float x) {
    float y; asm("ex2.approx.f32 %0, %1;" : "=f"(y) : "f"(x)); return y;
}
__device__ __forceinline__ float tf32r(float x) {
    float y; asm("cvt.rna.tf32.f32 %0, %1;" : "=f"(y) : "f"(x)); return y;
}
__device__ __forceinline__ void ldsm4(u32& r0, u32& r1, u32& r2, u32& r3, u32 a) {
    asm volatile("ldmatrix.sync.aligned.m8n8.x4.shared.b16 {%0,%1,%2,%3}, [%4];"
                 : "=r"(r0), "=r"(r1), "=r"(r2), "=r"(r3) : "r"(a));
}
__device__ __forceinline__ void ldsm4t(u32& r0, u32& r1, u32& r2, u32& r3, u32 a) {
    asm volatile("ldmatrix.sync.aligned.m8n8.x4.trans.shared.b16 {%0,%1,%2,%3}, [%4];"
                 : "=r"(r0), "=r"(r1), "=r"(r2), "=r"(r3) : "r"(a));
}
__device__ __forceinline__ void mma16816(float* d, const u32* a, const u32* b) {
    asm volatile(
        "mma.sync.aligned.m16n8k16.row.col.f32.bf16.bf16.f32 "
        "{%0,%1,%2,%3}, {%4,%5,%6,%7}, {%8,%9}, {%0,%1,%2,%3};"
        : "+f"(d[0]), "+f"(d[1]), "+f"(d[2]), "+f"(d[3])
        : "r"(a[0]), "r"(a[1]), "r"(a[2]), "r"(a[3]), "r"(b[0]), "r"(b[1]));
}
__device__ __forceinline__ void mma_tf32(float* d, const u32* a, const u32* b) {
    asm volatile(
        "mma.sync.aligned.m16n8k8.row.col.f32.tf32.tf32.f32 "
        "{%0,%1,%2,%3}, {%4,%5,%6,%7}, {%8,%9}, {%0,%1,%2,%3};"
        : "+f"(d[0]), "+f"(d[1]), "+f"(d[2]), "+f"(d[3])
        : "r"(a[0]), "r"(a[1]), "r"(a[2]), "r"(a[3]), "r"(b[0]), "r"(b[1]));
}
__device__ __forceinline__ u32 pkbf(float lo, float hi) {
    bf162 t = __halves2bfloat162(__float2bfloat16(lo), __float2bfloat16(hi));
    return *(u32*)&t;
}
// swizzled byte offset in a [rows x 128B] tile (SW128 style)
__device__ __forceinline__ u32 swz(int r, int c) {
    return (u32)(r * 128 + ((c ^ (r & 7)) * 16));
}

// ============================================================================
// Conversion kernels
// ============================================================================
__global__ __launch_bounds__(256) void conv_x_tf32(const float* __restrict__ in, int n4)
{
    int i = blockIdx.x * 256 + threadIdx.x;
    if (i >= n4) return;
    float4 v = ((const float4*)in)[i];
    v.x = tf32r(v.x); v.y = tf32r(v.y); v.z = tf32r(v.z); v.w = tf32r(v.w);
    ((float4*)g_xtf)[i] = v;
}

template<int WSEL>    // 0 -> g_wq (attn weight), 1 -> g_wp (proj weight)
__global__ __launch_bounds__(256) void conv_transpose_tf32(const float* __restrict__ w,
                                                           int K, int N)
{
    float* dst = WSEL ? g_wp : g_wq;
    __shared__ float t[32][33];
    const int n0 = blockIdx.x * 32, k0 = blockIdx.y * 32;
    const int x = threadIdx.x & 31, y = (threadIdx.x >> 5) * 4;
#pragma unroll
    for (int r = 0; r < 4; ++r)
        t[y + r][x] = w[(size_t)(k0 + y + r) * N + n0 + x];
    __syncthreads();
#pragma unroll
    for (int r = 0; r < 4; ++r) {
        const int n = n0 + y + r, kk = k0 + x;
        dst[(size_t)n * K + kk] = tf32r(t[x][y + r]);
    }
}

// ============================================================================
// TF32 single-pass GEMM via mma.sync.m16n8k8. 128x128 CTA, 8 warps (64x32),
// BK=32 (4 k8 steps), 3 stages x 32KB = 96KB -> 2 CTAs/SM, 1 sync/chunk.
// A tile [128 m][32 k] fp32 (SW128 rows), B tile [128 n][32 k] fp32.
// A frags via ldmatrix.b16 (bit-equivalent); B frags via conflict-free LDS.32.
// MODE 0: qkv -> bf16 hi/lo scatter (Q scaled).  MODE 1: proj -> fp32 out.
// ============================================================================
template<int MODE>
__global__ __launch_bounds__(256, 2) void mma_gemm(const float* __restrict__ bias,
                                                   float* __restrict__ outp)
{
    extern __shared__ char smem[];
    const u32 sb = smem_u32(smem);
    const int tx = threadIdx.x, wid = tx >> 5, lane = tx & 31;
    const int m0 = blockIdx.y * 128, n0 = blockIdx.x * 128;
    const int K = DM;
    const int NCH = K / 32;                 // 32 chunks

    const float* Ag = MODE ? g_atf : g_xtf;
    const float* Bg = MODE ? g_wp  : g_wq;

    const int wm = (wid & 1) * 64;
    const int wn = (wid >> 1) * 32;

    auto load_chunk = [&](int ci, int stage) {
        const int k0 = ci * 32;
#pragma unroll
        for (int t = 0; t < 2; ++t) {
            const float* src = t ? Bg : Ag;
            const int rbase  = t ? n0 : m0;
            const u32 tb = sb + (u32)(stage * 32768 + t * 16384);
#pragma unroll
            for (int u = 0; u < 4; ++u) {
                const int id = tx + 256 * u;
                const int r = id >> 3, c = id & 7;
                cp_async16(tb + swz(r, c),
                           src + (size_t)(rbase + r) * K + k0 + c * 4);
            }
        }
        cp_commit();
    };

    float acc[4][4][4];
#pragma unroll
    for (int mt = 0; mt < 4; ++mt)
#pragma unroll
        for (int nt = 0; nt < 4; ++nt)
#pragma unroll
            for (int e = 0; e < 4; ++e) acc[mt][nt][e] = 0.f;

    load_chunk(0, 0);
    load_chunk(1, 1);

    const int a_lrow = lane & 15;
    const int a_lc   = lane >> 4;
    const int b_ln   = lane >> 2;          // 0..7  (n within n8)
    const int b_lk   = lane & 3;           // 0..3  (k within k4 group)

    for (int i = 0; i < NCH; ++i) {
        const int s = i % 3;
        if (i + 1 < NCH) cp_wait1(); else cp_wait0();
        __syncthreads();
        if (i + 2 < NCH) load_chunk(i + 2, (i + 2) % 3);

        const u32 tA = sb + (u32)(s * 32768);
        const char* pB = smem + s * 32768 + 16384;

#pragma unroll
        for (int ks = 0; ks < 4; ++ks) {
            u32 af[4][4];
#pragma unroll
            for (int mt = 0; mt < 4; ++mt) {
                const int row = wm + mt * 16 + a_lrow;
                ldsm4(af[mt][0], af[mt][1], af[mt][2], af[mt][3],
                      tA + swz(row, ks * 2 + a_lc));
            }
            u32 bfr[4][2];
#pragma unroll
            for (int nt = 0; nt < 4; ++nt) {
                const int bn = wn + nt * 8 + b_ln;
                const u32 o0 = (u32)(bn * 128 + (((ks*2)   ^ (bn & 7)) * 16) + b_lk * 4);
                const u32 o1 = (u32)(bn * 128 + (((ks*2+1) ^ (bn & 7)) * 16) + b_lk * 4);
                bfr[nt][0] = *(const u32*)(pB + o0);
                bfr[nt][1] = *(const u32*)(pB + o1);
            }
#pragma unroll
            for (int mt = 0; mt < 4; ++mt)
#pragma unroll
                for (int nt = 0; nt < 4; ++nt)
                    mma_tf32(acc[mt][nt], af[mt], bfr[nt]);
        }
    }

    const int r_in  = lane >> 2;
    const int cpair = (lane & 3) * 2;

    if (MODE == 0) {
        const int seg = n0 >> 10;
        bf16 *dhi, *dlo;
        if (seg == 0)      { dhi = g_qhi; dlo = g_qlo; }
        else if (seg == 1) { dhi = g_khi; dlo = g_klo; }
        else               { dhi = g_vhi; dlo = g_vlo; }
        const float qs = (seg == 0) ? QSCALE : 1.0f;
#pragma unroll
        for (int mt = 0; mt < 4; ++mt)
#pragma unroll
            for (int nt = 0; nt < 4; ++nt)
#pragma unroll
                for (int hh = 0; hh < 2; ++hh) {
                    const int m = m0 + wm + mt * 16 + r_in + hh * 8;
                    const int n = n0 + wn + nt * 8 + cpair;
                    const int b  = m >> 11;
                    const int sI = m & 2047;
                    const int nn = n & 1023;
                    const int h  = nn >> 6, dd = nn & 63;
                    const float vx = (acc[mt][nt][hh*2+0] + bias[n]) * qs;
                    const float vy = (acc[mt][nt][hh*2+1] + bias[n+1]) * qs;
                    const bf16 hx = __float2bfloat16(vx);
                    const bf16 hy = __float2bfloat16(vy);
                    const size_t idx = ((((size_t)b * NH + h) * SQ + sI) << 6) + dd;
                    *(bf162*)(dhi + idx) = __halves2bfloat162(hx, hy);
                    *(bf162*)(dlo + idx) = __halves2bfloat162(
                        __float2bfloat16(vx - __bfloat162float(hx)),
                        __float2bfloat16(vy - __bfloat162float(hy)));
                }
    } else {
#pragma unroll
        for (int mt = 0; mt < 4; ++mt)
#pragma unroll
            for (int nt = 0; nt < 4; ++nt)
#pragma unroll
                for (int hh = 0; hh < 2; ++hh) {
                    const int m = m0 + wm + mt * 16 + r_in + hh * 8;
                    const int n = n0 + wn + nt * 8 + cpair;
                    float2 v;
                    v.x = acc[mt][nt][hh * 2 + 0] + bias[n];
                    v.y = acc[mt][nt][hh * 2 + 1] + bias[n + 1];
                    *(float2*)(outp + (size_t)m * DM + n) = v;
                }
    }
}

// ============================================================================
// Tensor-core flash attention (bf16x3, unchanged core). CTA = 128 q-rows x
// one (b,h). 8 warps. K-chunks of 64 keys, 2 stages, 96KB -> 2 CTAs/SM.
// Epilogue writes merged output as tf32-rounded fp32 into g_atf.
// ============================================================================
__global__ __launch_bounds__(256, 2) void attn_mma()
{
    extern __shared__ char smem[];
    const u32 sb = smem_u32(smem);
    const int tx = threadIdx.x, wid = tx >> 5, lane = tx & 31;
    const int qt = blockIdx.x, bh = blockIdx.y;
    const int q0 = qt * 128;
    const int wm = wid * 16;
    const size_t base = (size_t)bh * SQ * HD;

    const bf16* Qh = g_qhi + base;
    const bf16* Ql = g_qlo + base;
    const bf16* Kh = g_khi + base;
    const bf16* Kl = g_klo + base;
    const bf16* Vh = g_vhi + base;
    const bf16* Vl = g_vlo + base;

#pragma unroll
    for (int u = 0; u < 4; ++u) {
        const int id = tx + 256 * u;
        const int r = id >> 3, c = id & 7;
        cp_async16(sb + swz(r, c),         Qh + (size_t)(q0 + r) * HD + c * 8);
        cp_async16(sb + 16384 + swz(r, c), Ql + (size_t)(q0 + r) * HD + c * 8);
    }
    auto load_chunk = [&](int kt, int s) {
        const int k0 = kt * 64;
        const u32 st = sb + 32768 + (u32)s * 32768;
#pragma unroll
        for (int u = 0; u < 2; ++u) {
            const int id = tx + 256 * u;
            const int r = id >> 3, c = id & 7;
            cp_async16(st + swz(r, c),          Kh + (size_t)(k0 + r) * HD + c * 8);
            cp_async16(st + 8192 + swz(r, c),   Kl + (size_t)(k0 + r) * HD + c * 8);
            cp_async16(st + 16384 + swz(r, c),  Vh + (size_t)(k0 + r) * HD + c * 8);
            cp_async16(st + 24576 + swz(r, c),  Vl + (size_t)(k0 + r) * HD + c * 8);
        }
        cp_commit();
    };
    load_chunk(0, 0);                 // group includes Q loads
    const int NCH = 2 * qt + 2;
    if (NCH > 1) load_chunk(1, 1);

    float O[8][4];
#pragma unroll
    for (int jn = 0; jn < 8; ++jn)
#pragma unroll
        for (int e = 0; e < 4; ++e) O[jn][e] = 0.f;
    float mrow[2] = {-1e30f, -1e30f};
    float lrow[2] = {0.f, 0.f};

    const int a_lrow = lane & 15;
    const int a_lc   = lane >> 4;
    const int b_lrow = lane & 7;
    const int b_lc   = (lane >> 3) & 1;
    const int b_sub  = (lane >> 4) & 1;

    for (int kt = 0; kt < NCH; ++kt) {
        const int s = kt & 1;
        const int k0 = kt * 64;
        if (kt + 1 < NCH) cp_wait1(); else cp_wait0();
        __syncthreads();

        const bool active = (k0 <= q0 + wm + 15);
        if (active) {
            const u32 stK  = sb + 32768 + (u32)s * 32768;
            const u32 stKl = stK + 8192;
            const u32 stV  = stK + 16384;
            const u32 stVl = stK + 24576;

            float S[8][4];
#pragma unroll
            for (int n = 0; n < 8; ++n)
#pragma unroll
                for (int e = 0; e < 4; ++e) S[n][e] = 0.f;

#pragma unroll
            for (int kt2 = 0; kt2 < 4; ++kt2) {
                u32 qh[4], ql[4];
                {
                    const u32 a = swz(wm + a_lrow, kt2 * 2 + a_lc);
                    ldsm4(qh[0], qh[1], qh[2], qh[3], sb + a);
                    ldsm4(ql[0], ql[1], ql[2], ql[3], sb + 16384 + a);
                }
#pragma unroll
                for (int p = 0; p < 4; ++p) {
                    const int row = p * 16 + b_sub * 8 + b_lrow;
                    const u32 a = swz(row, kt2 * 2 + b_lc);
                    u32 k0b[2], k1b[2], k0l[2], k1l[2];
                    ldsm4(k0b[0], k0b[1], k1b[0], k1b[1], stK + a);
                    ldsm4(k0l[0], k0l[1], k1l[0], k1l[1], stKl + a);
                    mma16816(S[2*p],   qh, k0b);
                    mma16816(S[2*p],   qh, k0l);
                    mma16816(S[2*p],   ql, k0b);
                    mma16816(S[2*p+1], qh, k1b);
                    mma16816(S[2*p+1], qh, k1l);
                    mma16816(S[2*p+1], ql, k1b);
                }
            }

            if (k0 + 63 > q0 + wm) {
                const int r0g = q0 + wm + (lane >> 2);
                const int cb  = k0 + (lane & 3) * 2;
#pragma unroll
                for (int n = 0; n < 8; ++n)
#pragma unroll
                    for (int e = 0; e < 2; ++e) {
                        const int col = cb + n * 8 + e;
                        if (col > r0g)     S[n][e]     = -1e30f;
                        if (col > r0g + 8) S[n][2 + e] = -1e30f;
                    }
            }

            float m0n = mrow[0], m1n = mrow[1];
#pragma unroll
            for (int n = 0; n < 8; ++n) {
                m0n = fmaxf(m0n, fmaxf(S[n][0], S[n][1]));
                m1n = fmaxf(m1n, fmaxf(S[n][2], S[n][3]));
            }
            m0n = fmaxf(m0n, __shfl_xor_sync(0xffffffffu, m0n, 1));
            m0n = fmaxf(m0n, __shfl_xor_sync(0xffffffffu, m0n, 2));
            m1n = fmaxf(m1n, __shfl_xor_sync(0xffffffffu, m1n, 1));
            m1n = fmaxf(m1n, __shfl_xor_sync(0xffffffffu, m1n, 2));

            const float sc0 = ex2(mrow[0] - m0n);
            const float sc1 = ex2(mrow[1] - m1n);
            mrow[0] = m0n; mrow[1] = m1n;

            float ps0 = 0.f, ps1 = 0.f;
#pragma unroll
            for (int n = 0; n < 8; ++n) {
                S[n][0] = ex2(S[n][0] - m0n); ps0 += S[n][0];
                S[n][1] = ex2(S[n][1] - m0n); ps0 += S[n][1];
                S[n][2] = ex2(S[n][2] - m1n); ps1 += S[n][2];
                S[n][3] = ex2(S[n][3] - m1n); ps1 += S[n][3];
            }
            ps0 += __shfl_xor_sync(0xffffffffu, ps0, 1);
            ps0 += __shfl_xor_sync(0xffffffffu, ps0, 2);
            ps1 += __shfl_xor_sync(0xffffffffu, ps1, 1);
            ps1 += __shfl_xor_sync(0xffffffffu, ps1, 2);
            lrow[0] = lrow[0] * sc0 + ps0;
            lrow[1] = lrow[1] * sc1 + ps1;
#pragma unroll
            for (int jn = 0; jn < 8; ++jn) {
                O[jn][0] *= sc0; O[jn][1] *= sc0;
                O[jn][2] *= sc1; O[jn][3] *= sc1;
            }

#pragma unroll
            for (int kt2 = 0; kt2 < 4; ++kt2) {
                u32 ph[4], pl[4];
                {
                    const int n0i = 2 * kt2, n1i = 2 * kt2 + 1;
                    ph[0] = pkbf(S[n0i][0], S[n0i][1]);
                    ph[1] = pkbf(S[n0i][2], S[n0i][3]);
                    ph[2] = pkbf(S[n1i][0], S[n1i][1]);
                    ph[3] = pkbf(S[n1i][2], S[n1i][3]);
                    const float h00 = __bfloat162float(__float2bfloat16(S[n0i][0]));
                    const float h01 = __bfloat162float(__float2bfloat16(S[n0i][1]));
                    const float h10 = __bfloat162float(__float2bfloat16(S[n0i][2]));
                    const float h11 = __bfloat162float(__float2bfloat16(S[n0i][3]));
                    const float h20 = __bfloat162float(__float2bfloat16(S[n1i][0]));
                    const float h21 = __bfloat162float(__float2bfloat16(S[n1i][1]));
                    const float h30 = __bfloat162float(__float2bfloat16(S[n1i][2]));
                    const float h31 = __bfloat162float(__float2bfloat16(S[n1i][3]));
                    pl[0] = pkbf(S[n0i][0] - h00, S[n0i][1] - h01);
                    pl[1] = pkbf(S[n0i][2] - h10, S[n0i][3] - h11);
                    pl[2] = pkbf(S[n1i][0] - h20, S[n1i][1] - h21);
                    pl[3] = pkbf(S[n1i][2] - h30, S[n1i][3] - h31);
                }
#pragma unroll
                for (int jp = 0; jp < 4; ++jp) {
                    const u32 a = swz(kt2 * 16 + a_lrow, jp * 2 + ((lane >> 4) & 1));
                    u32 v0[2], v1[2], vl0[2], vl1[2];
                    ldsm4t(v0[0], v0[1], v1[0], v1[1], stV + a);
                    ldsm4t(vl0[0], vl0[1], vl1[0], vl1[1], stVl + a);
                    mma16816(O[2*jp],   ph, v0);
                    mma16816(O[2*jp],   ph, vl0);
                    mma16816(O[2*jp],   pl, v0);
                    mma16816(O[2*jp+1], ph, v1);
                    mma16816(O[2*jp+1], ph, vl1);
                    mma16816(O[2*jp+1], pl, v1);
                }
            }
        }

        __syncthreads();
        if (kt + 2 < NCH) load_chunk(kt + 2, s);
    }

    // ---- epilogue: normalize, tf32-round, write g_atf [b,s,h*64+dd] fp32
    const int b = bh >> 4, h = bh & 15;
    const float inv0 = 1.0f / lrow[0];
    const float inv1 = 1.0f / lrow[1];
    const int r0g = q0 + wm + (lane >> 2);
    const int colb = h * 64 + (lane & 3) * 2;
#pragma unroll
    for (int jn = 0; jn < 8; ++jn) {
        const int col = colb + jn * 8;
        {
            float2 v;
            v.x = tf32r(O[jn][0] * inv0);
            v.y = tf32r(O[jn][1] * inv0);
            *(float2*)(g_atf + ((size_t)b * SQ + r0g) * DM + col) = v;
        }
        {
            float2 v;
            v.x = tf32r(O[jn][2] * inv1);
            v.y = tf32r(O[jn][3] * inv1);
            *(float2*)(g_atf + ((size_t)b * SQ + r0g + 8) * DM + col) = v;
        }
    }
}

// ============================================================================
extern "C" void kernel_launch(void* const* d_in, const int* in_sizes, int n_in,
                              void* d_out, int out_size)
{
    const float* x    = (const float*)d_in[0];
    const float* attw = (const float*)d_in[1];
    const float* attb = (const float*)d_in[2];
    const float* pw   = (const float*)d_in[3];
    const float* pb   = (const float*)d_in[4];
    float* out = (float*)d_out;

    const int MMA_SMEM  = 3 * 32768;          // 98304 -> 2 CTAs/SM
    const int ATTN_SMEM = 32768 + 2 * 32768;  // 98304 -> 2 CTAs/SM
    cudaFuncSetAttribute(mma_gemm<0>,
        cudaFuncAttributeMaxDynamicSharedMemorySize, MMA_SMEM);
    cudaFuncSetAttribute(mma_gemm<1>,
        cudaFuncAttributeMaxDynamicSharedMemorySize, MMA_SMEM);
    cudaFuncSetAttribute(attn_mma,
        cudaFuncAttributeMaxDynamicSharedMemorySize, ATTN_SMEM);

    const int n4 = BS * DM / 4;

    conv_x_tf32<<<(n4 + 255) / 256, 256>>>(x, n4);
    conv_transpose_tf32<0><<<dim3(N3 / 32, DM / 32), 256>>>(attw, DM, N3);
    conv_transpose_tf32<1><<<dim3(DM / 32, DM / 32), 256>>>(pw, DM, DM);

    mma_gemm<0><<<dim3(N3 / 128, BS / 128), 256, MMA_SMEM>>>(attb, nullptr);

    attn_mma<<<dim3(SQ / 128, BB * NH), 256, ATTN_SMEM>>>();

    mma_gemm<1><<<dim3(DM / 128, BS / 128), 256, MMA_SMEM>>>(pb, out);
}